// round 2
// baseline (speedup 1.0000x reference)
#include <cuda_runtime.h>
#include <cstdint>

// Problem-shape caps (from reference setup_inputs)
#define NMAX 100000
#define EMAX 1000000
#define ETMAX (EMAX + NMAX)

// ---------------- scratch (device globals: allocation-free rule) -------------
__device__ float    g_xl[(size_t)NMAX * 128];
__device__ float    g_xr[(size_t)NMAX * 128];
__device__ float    g_h [(size_t)NMAX * 128];
__device__ float    g_acc[(size_t)NMAX * 128];
__device__ float    g_score[(size_t)ETMAX * 4];
__device__ unsigned g_max[(size_t)NMAX * 4];
__device__ float    g_sum[(size_t)NMAX * 4];

// ---------------- helpers ----------------------------------------------------
__device__ __forceinline__ unsigned enc_f(float f) {
    unsigned u = __float_as_uint(f);
    return (u & 0x80000000u) ? ~u : (u | 0x80000000u);
}
__device__ __forceinline__ float dec_f(unsigned u) {
    return (u & 0x80000000u) ? __uint_as_float(u & 0x7fffffffu)
                             : __uint_as_float(~u);
}
__device__ __forceinline__ float lrelu(float v) { return v > 0.f ? v : 0.2f * v; }

__device__ __forceinline__ void red_add_v4(float* p, float4 v) {
    asm volatile("red.global.add.v4.f32 [%0], {%1,%2,%3,%4};"
                 :: "l"(p), "f"(v.x), "f"(v.y), "f"(v.z), "f"(v.w) : "memory");
}

// ---------------- fused dual GEMM:  y = in @ [Wl;Wr]^T + [bl;br] -------------
// in: [N,128]; Wl/Wr: [Jhalf,128]; outputs xl/xr: [N,Jhalf]
// COLS4*4 = 2*Jhalf total output cols, threads = COLS4*ROWG, rows/tile = ROWG*8
template<int COLS4, int ROWG>
__global__ __launch_bounds__(COLS4 * ROWG, 1)
void gemm_dual(const float* __restrict__ in, int N,
               const float* __restrict__ Wl, const float* __restrict__ bl,
               const float* __restrict__ Wr, const float* __restrict__ br,
               int Jhalf,
               float* __restrict__ xl, float* __restrict__ xr)
{
    constexpr int J   = COLS4 * 4;
    constexpr int RPT = ROWG * 8;
    extern __shared__ float sm[];
    float* Wt   = sm;                 // [128][J]  (k-major, col contiguous)
    float* bcol = Wt + 128 * J;       // [J]
    float* xs   = bcol + J;           // [RPT][129]  (pad avoids bank conflicts)

    const int tid = threadIdx.x;
    const int nth = blockDim.x;

    for (int idx = tid; idx < 128 * J; idx += nth) {
        int k = idx / J, j = idx % J;
        Wt[idx] = (j < Jhalf) ? Wl[j * 128 + k] : Wr[(j - Jhalf) * 128 + k];
    }
    for (int j = tid; j < J; j += nth)
        bcol[j] = (j < Jhalf) ? bl[j] : br[j - Jhalf];
    __syncthreads();

    const int cg = tid % COLS4;       // 4-col group
    const int rg = tid / COLS4;       // row group
    const int ntiles = (N + RPT - 1) / RPT;

    for (int tile = blockIdx.x; tile < ntiles; tile += gridDim.x) {
        const int r0 = tile * RPT;
        for (int idx = tid; idx < RPT * 128; idx += nth) {
            int r = idx >> 7, k = idx & 127;
            int row = r0 + r;
            xs[r * 129 + k] = (row < N) ? in[(size_t)row * 128 + k] : 0.f;
        }
        __syncthreads();

        float acc[8][4];
        #pragma unroll
        for (int r = 0; r < 8; r++)
            acc[r][0] = acc[r][1] = acc[r][2] = acc[r][3] = 0.f;

        const float* xsb = xs + (rg * 8) * 129;
        #pragma unroll 4
        for (int k = 0; k < 128; k++) {
            float4 w = reinterpret_cast<const float4*>(Wt + k * J)[cg];
            #pragma unroll
            for (int r = 0; r < 8; r++) {
                float xv = xsb[r * 129 + k];
                acc[r][0] += w.x * xv;
                acc[r][1] += w.y * xv;
                acc[r][2] += w.z * xv;
                acc[r][3] += w.w * xv;
            }
        }

        const int j0 = cg * 4;
        float4 bv = reinterpret_cast<const float4*>(bcol)[cg];
        float* outbase;
        int jo;
        if (j0 < Jhalf) { outbase = xl; jo = j0; }
        else            { outbase = xr; jo = j0 - Jhalf; }

        #pragma unroll
        for (int r = 0; r < 8; r++) {
            int row = r0 + rg * 8 + r;
            if (row < N) {
                float4 v = make_float4(acc[r][0] + bv.x, acc[r][1] + bv.y,
                                       acc[r][2] + bv.z, acc[r][3] + bv.w);
                *reinterpret_cast<float4*>(outbase + (size_t)row * Jhalf + jo) = v;
            }
        }
        __syncthreads();
    }
}

// ---------------- edge kernels, H=4, C=32 (layers 1 & 2) --------------------
__global__ void score_h4(const float* __restrict__ xl, const float* __restrict__ xr,
                         const int* __restrict__ ei, int E, int ET,
                         const float* __restrict__ att,
                         float* __restrict__ score, unsigned* __restrict__ maxb)
{
    int w = (int)((blockIdx.x * (unsigned)blockDim.x + threadIdx.x) >> 5);
    if (w >= ET) return;
    int lane = threadIdx.x & 31;
    int src, dst;
    if (w < E) { src = ei[w]; dst = ei[E + w]; } else { src = dst = w - E; }

    float4 a = *reinterpret_cast<const float4*>(xl + (size_t)src * 128 + lane * 4);
    float4 b = *reinterpret_cast<const float4*>(xr + (size_t)dst * 128 + lane * 4);
    float4 av = *reinterpret_cast<const float4*>(att + lane * 4);
    float p = lrelu(a.x + b.x) * av.x + lrelu(a.y + b.y) * av.y
            + lrelu(a.z + b.z) * av.z + lrelu(a.w + b.w) * av.w;
    p += __shfl_xor_sync(0xffffffffu, p, 1);
    p += __shfl_xor_sync(0xffffffffu, p, 2);
    p += __shfl_xor_sync(0xffffffffu, p, 4);
    if ((lane & 7) == 0) {
        int h = lane >> 3;
        score[(size_t)w * 4 + h] = p;
        atomicMax(&maxb[(size_t)dst * 4 + h], enc_f(p));
    }
}

// one thread per EDGE: vector ld/st of the 4 head scores, single dst read
__global__ void expsum_h4(float* __restrict__ score, const int* __restrict__ ei,
                          int E, int ET,
                          const unsigned* __restrict__ maxb, float* __restrict__ sumb)
{
    int e = blockIdx.x * blockDim.x + threadIdx.x;
    if (e >= ET) return;
    int dst = (e < E) ? ei[E + e] : e - E;
    float4 s = *reinterpret_cast<float4*>(score + (size_t)e * 4);
    const unsigned* mb = maxb + (size_t)dst * 4;
    float* sb = sumb + (size_t)dst * 4;
    float p0 = __expf(s.x - dec_f(mb[0]));
    float p1 = __expf(s.y - dec_f(mb[1]));
    float p2 = __expf(s.z - dec_f(mb[2]));
    float p3 = __expf(s.w - dec_f(mb[3]));
    *reinterpret_cast<float4*>(score + (size_t)e * 4) = make_float4(p0, p1, p2, p3);
    atomicAdd(sb + 0, p0);
    atomicAdd(sb + 1, p1);
    atomicAdd(sb + 2, p2);
    atomicAdd(sb + 3, p3);
}

__global__ void agg_h4(const float* __restrict__ xl, const float* __restrict__ score,
                       const float* __restrict__ sumb, const int* __restrict__ ei,
                       int E, int ET, float* __restrict__ out)
{
    int w = (int)((blockIdx.x * (unsigned)blockDim.x + threadIdx.x) >> 5);
    if (w >= ET) return;
    int lane = threadIdx.x & 31;
    int src, dst;
    if (w < E) { src = ei[w]; dst = ei[E + w]; } else { src = dst = w - E; }
    int h = lane >> 3;
    float alpha = score[(size_t)w * 4 + h] / sumb[(size_t)dst * 4 + h];
    float4 v = *reinterpret_cast<const float4*>(xl + (size_t)src * 128 + lane * 4);
    v.x *= alpha; v.y *= alpha; v.z *= alpha; v.w *= alpha;
    red_add_v4(out + (size_t)dst * 128 + lane * 4, v);
}

// ---------------- edge kernels, H=1, C=40 (layer 3) -------------------------
__global__ void score_h1(const float* __restrict__ xl, const float* __restrict__ xr,
                         const int* __restrict__ ei, int E, int ET,
                         const float* __restrict__ att,
                         float* __restrict__ score, unsigned* __restrict__ maxb)
{
    int w = (int)((blockIdx.x * (unsigned)blockDim.x + threadIdx.x) >> 5);
    if (w >= ET) return;
    int lane = threadIdx.x & 31;
    int src, dst;
    if (w < E) { src = ei[w]; dst = ei[E + w]; } else { src = dst = w - E; }

    const float* xls = xl + (size_t)src * 40;
    const float* xrd = xr + (size_t)dst * 40;
    float p = lrelu(xls[lane] + xrd[lane]) * att[lane];
    if (lane < 8)
        p += lrelu(xls[lane + 32] + xrd[lane + 32]) * att[lane + 32];
    p += __shfl_xor_sync(0xffffffffu, p, 16);
    p += __shfl_xor_sync(0xffffffffu, p, 8);
    p += __shfl_xor_sync(0xffffffffu, p, 4);
    p += __shfl_xor_sync(0xffffffffu, p, 2);
    p += __shfl_xor_sync(0xffffffffu, p, 1);
    if (lane == 0) {
        score[w] = p;
        atomicMax(&maxb[dst], enc_f(p));
    }
}

__global__ void expsum_h1(float* __restrict__ score, const int* __restrict__ ei,
                          int E, int ET,
                          const unsigned* __restrict__ maxb, float* __restrict__ sumb)
{
    int e = blockIdx.x * blockDim.x + threadIdx.x;
    if (e >= ET) return;
    int dst = (e < E) ? ei[E + e] : e - E;
    float p = __expf(score[e] - dec_f(maxb[dst]));
    score[e] = p;
    atomicAdd(&sumb[dst], p);
}

__global__ void agg_h1(const float* __restrict__ xl, const float* __restrict__ score,
                       const float* __restrict__ sumb, const int* __restrict__ ei,
                       int E, int ET, float* __restrict__ out)
{
    int w = (int)((blockIdx.x * (unsigned)blockDim.x + threadIdx.x) >> 5);
    if (w >= ET) return;
    int lane = threadIdx.x & 31;
    int src, dst;
    if (w < E) { src = ei[w]; dst = ei[E + w]; } else { src = dst = w - E; }
    float alpha = score[w] / sumb[dst];
    const float* xls = xl + (size_t)src * 40;
    float* ob = out + (size_t)dst * 40;
    atomicAdd(ob + lane, alpha * xls[lane]);
    if (lane < 8)
        atomicAdd(ob + lane + 32, alpha * xls[lane + 32]);
}

// ---------------- elementwise epilogues -------------------------------------
__global__ void bias_elu(const float* __restrict__ in, const float* __restrict__ bias,
                         float* __restrict__ out, int total)
{
    int i = blockIdx.x * blockDim.x + threadIdx.x;
    if (i >= total) return;
    float o = in[i] + bias[i & 127];
    out[i] = o > 0.f ? o : expm1f(o);
}

__global__ void bias_only40(const float* __restrict__ in, const float* __restrict__ bias,
                            float* __restrict__ out, int total)
{
    int i = blockIdx.x * blockDim.x + threadIdx.x;
    if (i >= total) return;
    out[i] = in[i] + bias[i % 40];
}

// ---------------- host orchestration ----------------------------------------
static inline int ceil_div(int a, int b) { return (a + b - 1) / b; }

extern "C" void kernel_launch(void* const* d_in, const int* in_sizes, int n_in,
                              void* d_out, int out_size)
{
    const float* x   = (const float*)d_in[0];
    const int*   ei  = (const int*)  d_in[1];
    const float* W1l = (const float*)d_in[2];
    const float* b1l = (const float*)d_in[3];
    const float* W1r = (const float*)d_in[4];
    const float* b1r = (const float*)d_in[5];
    const float* at1 = (const float*)d_in[6];
    const float* bs1 = (const float*)d_in[7];
    const float* W2l = (const float*)d_in[8];
    const float* b2l = (const float*)d_in[9];
    const float* W2r = (const float*)d_in[10];
    const float* b2r = (const float*)d_in[11];
    const float* at2 = (const float*)d_in[12];
    const float* bs2 = (const float*)d_in[13];
    const float* W3l = (const float*)d_in[14];
    const float* b3l = (const float*)d_in[15];
    const float* W3r = (const float*)d_in[16];
    const float* b3r = (const float*)d_in[17];
    const float* at3 = (const float*)d_in[18];
    const float* bs3 = (const float*)d_in[19];
    float* out = (float*)d_out;

    const int N  = in_sizes[0] / 128;
    const int E  = in_sizes[1] / 2;
    const int ET = E + N;

    float *xl, *xr, *h, *acc, *score, *sum;
    unsigned* maxb;
    cudaGetSymbolAddress((void**)&xl,    g_xl);
    cudaGetSymbolAddress((void**)&xr,    g_xr);
    cudaGetSymbolAddress((void**)&h,     g_h);
    cudaGetSymbolAddress((void**)&acc,   g_acc);
    cudaGetSymbolAddress((void**)&score, g_score);
    cudaGetSymbolAddress((void**)&maxb,  g_max);
    cudaGetSymbolAddress((void**)&sum,   g_sum);

    const int SM12 = (128 * 256 + 256 + 32 * 129) * 4;   // 148608 B
    const int SM3  = (128 * 80 + 80 + 96 * 129) * 4;     //  90816 B
    cudaFuncSetAttribute(gemm_dual<64, 4>,  cudaFuncAttributeMaxDynamicSharedMemorySize, SM12);
    cudaFuncSetAttribute(gemm_dual<20, 12>, cudaFuncAttributeMaxDynamicSharedMemorySize, SM3);

    const int warpBlocks = ceil_div(ET, 8);         // 8 warps / 256-thread block

    // ===== layer 1 (H=4, C=32) =====
    gemm_dual<64, 4><<<148, 256, SM12>>>(x, N, W1l, b1l, W1r, b1r, 128, xl, xr);
    cudaMemsetAsync(maxb, 0, (size_t)N * 4 * sizeof(unsigned));
    cudaMemsetAsync(sum,  0, (size_t)N * 4 * sizeof(float));
    cudaMemsetAsync(acc,  0, (size_t)N * 128 * sizeof(float));
    score_h4 <<<warpBlocks, 256>>>(xl, xr, ei, E, ET, at1, score, maxb);
    expsum_h4<<<ceil_div(ET, 256), 256>>>(score, ei, E, ET, maxb, sum);
    agg_h4   <<<warpBlocks, 256>>>(xl, score, sum, ei, E, ET, acc);
    bias_elu <<<ceil_div(N * 128, 256), 256>>>(acc, bs1, h, N * 128);

    // ===== layer 2 (H=4, C=32) =====
    gemm_dual<64, 4><<<148, 256, SM12>>>(h, N, W2l, b2l, W2r, b2r, 128, xl, xr);
    cudaMemsetAsync(maxb, 0, (size_t)N * 4 * sizeof(unsigned));
    cudaMemsetAsync(sum,  0, (size_t)N * 4 * sizeof(float));
    cudaMemsetAsync(acc,  0, (size_t)N * 128 * sizeof(float));
    score_h4 <<<warpBlocks, 256>>>(xl, xr, ei, E, ET, at2, score, maxb);
    expsum_h4<<<ceil_div(ET, 256), 256>>>(score, ei, E, ET, maxb, sum);
    agg_h4   <<<warpBlocks, 256>>>(xl, score, sum, ei, E, ET, acc);
    bias_elu <<<ceil_div(N * 128, 256), 256>>>(acc, bs2, h, N * 128);

    // ===== layer 3 (H=1, C=40) =====
    gemm_dual<20, 12><<<148, 240, SM3>>>(h, N, W3l, b3l, W3r, b3r, 40, xl, xr);
    cudaMemsetAsync(maxb, 0, (size_t)N * sizeof(unsigned));
    cudaMemsetAsync(sum,  0, (size_t)N * sizeof(float));
    cudaMemsetAsync(acc,  0, (size_t)N * 40 * sizeof(float));
    score_h1 <<<warpBlocks, 256>>>(xl, xr, ei, E, ET, at3, score, maxb);
    expsum_h1<<<ceil_div(ET, 256), 256>>>(score, ei, E, ET, maxb, sum);
    agg_h1   <<<warpBlocks, 256>>>(xl, score, sum, ei, E, ET, acc);
    bias_only40<<<ceil_div(N * 40, 256), 256>>>(acc, bs3, out, N * 40);
}

// round 3
// speedup vs baseline: 1.4536x; 1.4536x over previous
#include <cuda_runtime.h>
#include <cstdint>

#define NMAX 100000
#define EMAX 1000000
#define ETMAX (EMAX + NMAX)

// ---------------- scratch (device globals: allocation-free rule) -------------
__device__ float g_xl[(size_t)NMAX * 128];
__device__ float g_xr[(size_t)NMAX * 128];
__device__ float g_h [(size_t)NMAX * 128];
__device__ float g_acc[(size_t)NMAX * 128];
__device__ float g_score[(size_t)ETMAX * 4];
__device__ float g_sum[(size_t)NMAX * 4];

// ---------------- helpers ----------------------------------------------------
__device__ __forceinline__ float lrelu(float v) { return v > 0.f ? v : 0.2f * v; }

__device__ __forceinline__ void red_add_v4(float* p, float4 v) {
    asm volatile("red.global.add.v4.f32 [%0], {%1,%2,%3,%4};"
                 :: "l"(p), "f"(v.x), "f"(v.y), "f"(v.z), "f"(v.w) : "memory");
}

// ---------------- fused dual GEMM:  y = in @ [Wl;Wr]^T + [bl;br] -------------
// J = COLG*8 total output cols (both halves), RPT = ROWG*8 rows per tile.
// threads = COLG*ROWG; each thread computes an 8x8 register tile.
template<int COLG, int ROWG>
__global__ __launch_bounds__(COLG * ROWG, 1)
void gemm_dual(const float* __restrict__ in, int N,
               const float* __restrict__ Wl, const float* __restrict__ bl,
               const float* __restrict__ Wr, const float* __restrict__ br,
               int Jhalf,
               float* __restrict__ xl, float* __restrict__ xr)
{
    constexpr int J     = COLG * 8;
    constexpr int RPT   = ROWG * 8;
    constexpr int XSPAD = 132;          // words per xs row (16B-aligned, de-banked)
    extern __shared__ float sm[];
    float* Wt   = sm;                   // [128][J]  k-major
    float* bcol = Wt + 128 * J;         // [J]
    float* xs   = bcol + J;             // [RPT][XSPAD]

    const int tid = threadIdx.x;
    const int nth = blockDim.x;

    for (int idx = tid; idx < 128 * J; idx += nth) {
        int k = idx / J, j = idx % J;
        Wt[idx] = (j < Jhalf) ? Wl[j * 128 + k] : Wr[(j - Jhalf) * 128 + k];
    }
    for (int j = tid; j < J; j += nth)
        bcol[j] = (j < Jhalf) ? bl[j] : br[j - Jhalf];
    __syncthreads();

    const int cg = tid % COLG;          // 8-col group
    const int rg = tid / COLG;          // 8-row group
    const int ntiles = (N + RPT - 1) / RPT;
    const float4* in4 = reinterpret_cast<const float4*>(in);

    for (int tile = blockIdx.x; tile < ntiles; tile += gridDim.x) {
        const int r0 = tile * RPT;
        for (int idx = tid; idx < RPT * 32; idx += nth) {
            int r = idx >> 5, k4 = idx & 31;
            int row = r0 + r;
            float4 v = (row < N) ? in4[(size_t)row * 32 + k4]
                                 : make_float4(0.f, 0.f, 0.f, 0.f);
            *reinterpret_cast<float4*>(xs + r * XSPAD + k4 * 4) = v;
        }
        __syncthreads();

        float acc[8][8];
        #pragma unroll
        for (int r = 0; r < 8; r++)
            #pragma unroll
            for (int c = 0; c < 8; c++) acc[r][c] = 0.f;

        const float* xsb = xs + (rg * 8) * XSPAD;
        const float* wb  = Wt + cg * 8;
        #pragma unroll 2
        for (int k = 0; k < 128; k++) {
            float4 w0 = *reinterpret_cast<const float4*>(wb + k * J);
            float4 w1 = *reinterpret_cast<const float4*>(wb + k * J + 4);
            #pragma unroll
            for (int r = 0; r < 8; r++) {
                float xv = xsb[r * XSPAD + k];
                acc[r][0] += w0.x * xv; acc[r][1] += w0.y * xv;
                acc[r][2] += w0.z * xv; acc[r][3] += w0.w * xv;
                acc[r][4] += w1.x * xv; acc[r][5] += w1.y * xv;
                acc[r][6] += w1.z * xv; acc[r][7] += w1.w * xv;
            }
        }

        const int j0 = cg * 8;
        float4 bv0 = *reinterpret_cast<const float4*>(bcol + j0);
        float4 bv1 = *reinterpret_cast<const float4*>(bcol + j0 + 4);
        float* outbase; int jo;
        if (j0 < Jhalf) { outbase = xl; jo = j0; }
        else            { outbase = xr; jo = j0 - Jhalf; }

        #pragma unroll
        for (int r = 0; r < 8; r++) {
            int row = r0 + rg * 8 + r;
            if (row < N) {
                float* op = outbase + (size_t)row * Jhalf + jo;
                *reinterpret_cast<float4*>(op) =
                    make_float4(acc[r][0] + bv0.x, acc[r][1] + bv0.y,
                                acc[r][2] + bv0.z, acc[r][3] + bv0.w);
                *reinterpret_cast<float4*>(op + 4) =
                    make_float4(acc[r][4] + bv1.x, acc[r][5] + bv1.y,
                                acc[r][6] + bv1.z, acc[r][7] + bv1.w);
            }
        }
        __syncthreads();
    }
}

// ---------------- fused score+exp+sum, H=4, C=32 (2 edges per warp) ---------
__global__ void score_h4(const float* __restrict__ xl, const float* __restrict__ xr,
                         const int* __restrict__ ei, int E, int ET,
                         const float* __restrict__ att,
                         float* __restrict__ score, float* __restrict__ sumb)
{
    unsigned gw = (blockIdx.x * (unsigned)blockDim.x + threadIdx.x) >> 5;
    int e0 = (int)(gw * 2);
    if (e0 >= ET) return;
    int e1 = e0 + 1;
    int lane = threadIdx.x & 31;
    int h = lane >> 3;

    int s0, d0;
    if (e0 < E) { s0 = ei[e0]; d0 = ei[E + e0]; } else { s0 = d0 = e0 - E; }
    int s1 = s0, d1 = d0;
    bool has1 = (e1 < ET);
    if (has1) { if (e1 < E) { s1 = ei[e1]; d1 = ei[E + e1]; } else { s1 = d1 = e1 - E; } }

    float4 av = *reinterpret_cast<const float4*>(att + lane * 4);
    float4 a0 = *reinterpret_cast<const float4*>(xl + (size_t)s0 * 128 + lane * 4);
    float4 b0 = *reinterpret_cast<const float4*>(xr + (size_t)d0 * 128 + lane * 4);
    float4 a1 = *reinterpret_cast<const float4*>(xl + (size_t)s1 * 128 + lane * 4);
    float4 b1 = *reinterpret_cast<const float4*>(xr + (size_t)d1 * 128 + lane * 4);

    float p0 = lrelu(a0.x + b0.x) * av.x + lrelu(a0.y + b0.y) * av.y
             + lrelu(a0.z + b0.z) * av.z + lrelu(a0.w + b0.w) * av.w;
    float p1 = lrelu(a1.x + b1.x) * av.x + lrelu(a1.y + b1.y) * av.y
             + lrelu(a1.z + b1.z) * av.z + lrelu(a1.w + b1.w) * av.w;

    #pragma unroll
    for (int o = 1; o < 8; o <<= 1) {
        p0 += __shfl_xor_sync(0xffffffffu, p0, o);
        p1 += __shfl_xor_sync(0xffffffffu, p1, o);
    }
    if ((lane & 7) == 0) {
        float q0 = __expf(p0);
        score[(size_t)e0 * 4 + h] = q0;
        atomicAdd(&sumb[(size_t)d0 * 4 + h], q0);
        if (has1) {
            float q1 = __expf(p1);
            score[(size_t)e1 * 4 + h] = q1;
            atomicAdd(&sumb[(size_t)d1 * 4 + h], q1);
        }
    }
}

// ---------------- aggregation, H=4 (2 edges per warp) -----------------------
__global__ void agg_h4(const float* __restrict__ xl, const float* __restrict__ score,
                       const float* __restrict__ sumb, const int* __restrict__ ei,
                       int E, int ET, float* __restrict__ out)
{
    unsigned gw = (blockIdx.x * (unsigned)blockDim.x + threadIdx.x) >> 5;
    int e0 = (int)(gw * 2);
    if (e0 >= ET) return;
    int e1 = e0 + 1;
    int lane = threadIdx.x & 31;
    int h = lane >> 3;

    int s0, d0;
    if (e0 < E) { s0 = ei[e0]; d0 = ei[E + e0]; } else { s0 = d0 = e0 - E; }
    int s1 = s0, d1 = d0;
    bool has1 = (e1 < ET);
    if (has1) { if (e1 < E) { s1 = ei[e1]; d1 = ei[E + e1]; } else { s1 = d1 = e1 - E; } }

    float p0 = score[(size_t)e0 * 4 + h];
    float z0 = sumb[(size_t)d0 * 4 + h];
    float4 v0 = *reinterpret_cast<const float4*>(xl + (size_t)s0 * 128 + lane * 4);
    float p1 = 0.f, z1 = 1.f;
    float4 v1 = make_float4(0.f, 0.f, 0.f, 0.f);
    if (has1) {
        p1 = score[(size_t)e1 * 4 + h];
        z1 = sumb[(size_t)d1 * 4 + h];
        v1 = *reinterpret_cast<const float4*>(xl + (size_t)s1 * 128 + lane * 4);
    }

    float a0 = p0 / z0;
    v0.x *= a0; v0.y *= a0; v0.z *= a0; v0.w *= a0;
    red_add_v4(out + (size_t)d0 * 128 + lane * 4, v0);
    if (has1) {
        float a1 = p1 / z1;
        v1.x *= a1; v1.y *= a1; v1.z *= a1; v1.w *= a1;
        red_add_v4(out + (size_t)d1 * 128 + lane * 4, v1);
    }
}

// ---------------- fused score+exp+sum, H=1, C=40 (2 edges per warp) ---------
// lanes [0..15] handle edge e0, lanes [16..31] edge e1; 10 active lanes each.
__global__ void score_h1(const float* __restrict__ xl, const float* __restrict__ xr,
                         const int* __restrict__ ei, int E, int ET,
                         const float* __restrict__ att,
                         float* __restrict__ score, float* __restrict__ sumb)
{
    unsigned gw = (blockIdx.x * (unsigned)blockDim.x + threadIdx.x) >> 5;
    int lane = threadIdx.x & 31;
    int grp  = lane >> 4;               // 0 or 1
    int gl   = lane & 15;
    int e = (int)(gw * 2) + grp;
    bool valid = (e < ET);
    int src = 0, dst = 0;
    if (valid) { if (e < E) { src = ei[e]; dst = ei[E + e]; } else { src = dst = e - E; } }

    float p = 0.f;
    if (valid && gl < 10) {
        float4 a = *reinterpret_cast<const float4*>(xl + (size_t)src * 40 + gl * 4);
        float4 b = *reinterpret_cast<const float4*>(xr + (size_t)dst * 40 + gl * 4);
        float4 t = *reinterpret_cast<const float4*>(att + gl * 4);
        p = lrelu(a.x + b.x) * t.x + lrelu(a.y + b.y) * t.y
          + lrelu(a.z + b.z) * t.z + lrelu(a.w + b.w) * t.w;
    }
    #pragma unroll
    for (int o = 8; o >= 1; o >>= 1)
        p += __shfl_xor_sync(0xffffffffu, p, o);
    if (valid && gl == 0) {
        float q = __expf(p);
        score[e] = q;
        atomicAdd(&sumb[dst], q);
    }
}

__global__ void agg_h1(const float* __restrict__ xl, const float* __restrict__ score,
                       const float* __restrict__ sumb, const int* __restrict__ ei,
                       int E, int ET, float* __restrict__ out)
{
    unsigned gw = (blockIdx.x * (unsigned)blockDim.x + threadIdx.x) >> 5;
    int lane = threadIdx.x & 31;
    int grp  = lane >> 4;
    int gl   = lane & 15;
    int e = (int)(gw * 2) + grp;
    if (e >= ET) return;
    int src, dst;
    if (e < E) { src = ei[e]; dst = ei[E + e]; } else { src = dst = e - E; }
    if (gl >= 10) return;
    float alpha = score[e] / sumb[dst];
    float4 v = *reinterpret_cast<const float4*>(xl + (size_t)src * 40 + gl * 4);
    v.x *= alpha; v.y *= alpha; v.z *= alpha; v.w *= alpha;
    red_add_v4(out + (size_t)dst * 40 + gl * 4, v);
}

// ---------------- elementwise epilogues (float4) ----------------------------
__global__ void bias_elu4(const float4* __restrict__ in, const float4* __restrict__ bias,
                          float4* __restrict__ out, int total4)
{
    int i = blockIdx.x * blockDim.x + threadIdx.x;
    if (i >= total4) return;
    float4 v = in[i], b = bias[i & 31];
    v.x += b.x; v.y += b.y; v.z += b.z; v.w += b.w;
    v.x = v.x > 0.f ? v.x : expm1f(v.x);
    v.y = v.y > 0.f ? v.y : expm1f(v.y);
    v.z = v.z > 0.f ? v.z : expm1f(v.z);
    v.w = v.w > 0.f ? v.w : expm1f(v.w);
    out[i] = v;
}

__global__ void bias40_4(const float4* __restrict__ in, const float4* __restrict__ bias,
                         float4* __restrict__ out, int total4)
{
    int i = blockIdx.x * blockDim.x + threadIdx.x;
    if (i >= total4) return;
    float4 v = in[i], b = bias[i % 10];
    v.x += b.x; v.y += b.y; v.z += b.z; v.w += b.w;
    out[i] = v;
}

// ---------------- host orchestration ----------------------------------------
static inline int ceil_div(int a, int b) { return (a + b - 1) / b; }

extern "C" void kernel_launch(void* const* d_in, const int* in_sizes, int n_in,
                              void* d_out, int out_size)
{
    const float* x   = (const float*)d_in[0];
    const int*   ei  = (const int*)  d_in[1];
    const float* W1l = (const float*)d_in[2];
    const float* b1l = (const float*)d_in[3];
    const float* W1r = (const float*)d_in[4];
    const float* b1r = (const float*)d_in[5];
    const float* at1 = (const float*)d_in[6];
    const float* bs1 = (const float*)d_in[7];
    const float* W2l = (const float*)d_in[8];
    const float* b2l = (const float*)d_in[9];
    const float* W2r = (const float*)d_in[10];
    const float* b2r = (const float*)d_in[11];
    const float* at2 = (const float*)d_in[12];
    const float* bs2 = (const float*)d_in[13];
    const float* W3l = (const float*)d_in[14];
    const float* b3l = (const float*)d_in[15];
    const float* W3r = (const float*)d_in[16];
    const float* b3r = (const float*)d_in[17];
    const float* at3 = (const float*)d_in[18];
    const float* bs3 = (const float*)d_in[19];
    float* out = (float*)d_out;

    const int N  = in_sizes[0] / 128;
    const int E  = in_sizes[1] / 2;
    const int ET = E + N;

    float *xl, *xr, *h, *acc, *score, *sum;
    cudaGetSymbolAddress((void**)&xl,    g_xl);
    cudaGetSymbolAddress((void**)&xr,    g_xr);
    cudaGetSymbolAddress((void**)&h,     g_h);
    cudaGetSymbolAddress((void**)&acc,   g_acc);
    cudaGetSymbolAddress((void**)&score, g_score);
    cudaGetSymbolAddress((void**)&sum,   g_sum);

    // gemm<32,8>: W 128x256 + bias 256 + xs 64x132
    const int SM12 = (128 * 256 + 256 + 64 * 132) * 4;   // 165888 B
    // gemm<10,16>: W 128x80 + bias 80 + xs 128x132
    const int SM3  = (128 * 80 + 80 + 128 * 132) * 4;    // 108864 B
    cudaFuncSetAttribute(gemm_dual<32, 8>,  cudaFuncAttributeMaxDynamicSharedMemorySize, SM12);
    cudaFuncSetAttribute(gemm_dual<10, 16>, cudaFuncAttributeMaxDynamicSharedMemorySize, SM3);

    // 2 edges per warp, 8 warps per 256-thread block -> 16 edges/block
    const int edgeBlocks = ceil_div(ET, 16);

    // ===== layer 1 (H=4, C=32) =====
    gemm_dual<32, 8><<<148, 256, SM12>>>(x, N, W1l, b1l, W1r, b1r, 128, xl, xr);
    cudaMemsetAsync(sum, 0, (size_t)N * 4 * sizeof(float));
    cudaMemsetAsync(acc, 0, (size_t)N * 128 * sizeof(float));
    score_h4<<<edgeBlocks, 256>>>(xl, xr, ei, E, ET, at1, score, sum);
    agg_h4  <<<edgeBlocks, 256>>>(xl, score, sum, ei, E, ET, acc);
    bias_elu4<<<ceil_div(N * 32, 256), 256>>>((const float4*)acc, (const float4*)bs1,
                                              (float4*)h, N * 32);

    // ===== layer 2 (H=4, C=32) =====
    gemm_dual<32, 8><<<148, 256, SM12>>>(h, N, W2l, b2l, W2r, b2r, 128, xl, xr);
    cudaMemsetAsync(sum, 0, (size_t)N * 4 * sizeof(float));
    cudaMemsetAsync(acc, 0, (size_t)N * 128 * sizeof(float));
    score_h4<<<edgeBlocks, 256>>>(xl, xr, ei, E, ET, at2, score, sum);
    agg_h4  <<<edgeBlocks, 256>>>(xl, score, sum, ei, E, ET, acc);
    bias_elu4<<<ceil_div(N * 32, 256), 256>>>((const float4*)acc, (const float4*)bs2,
                                              (float4*)h, N * 32);

    // ===== layer 3 (H=1, C=40) =====
    gemm_dual<10, 16><<<148, 160, SM3>>>(h, N, W3l, b3l, W3r, b3r, 40, xl, xr);
    cudaMemsetAsync(sum, 0, (size_t)N * sizeof(float));
    cudaMemsetAsync(acc, 0, (size_t)N * 40 * sizeof(float));
    score_h1<<<edgeBlocks, 256>>>(xl, xr, ei, E, ET, at3, score, sum);
    agg_h1  <<<edgeBlocks, 256>>>(xl, score, sum, ei, E, ET, acc);
    bias40_4<<<ceil_div(N * 10, 256), 256>>>((const float4*)acc, (const float4*)bs3,
                                             (float4*)out, N * 10);
}

// round 6
// speedup vs baseline: 1.6805x; 1.1561x over previous
#include <cuda_runtime.h>
#include <cstdint>

#define NMAX 100000
#define EMAX 1000000
#define ETMAX (EMAX + NMAX)

// ---------------- scratch (device globals: allocation-free rule) -------------
__device__ float g_xl[(size_t)NMAX * 128];
__device__ float g_xr[(size_t)NMAX * 128];
__device__ float g_h [(size_t)NMAX * 128];
__device__ float g_acc[(size_t)NMAX * 128];
__device__ float g_sum[(size_t)NMAX * 4];

// ---------------- helpers ----------------------------------------------------
__device__ __forceinline__ float lrelu(float v) { return v > 0.f ? v : 0.2f * v; }

__device__ __forceinline__ void red_add_v4(float* p, float4 v) {
    asm volatile("red.global.add.v4.f32 [%0], {%1,%2,%3,%4};"
                 :: "l"(p), "f"(v.x), "f"(v.y), "f"(v.z), "f"(v.w) : "memory");
}

// ---------------- fused dual GEMM:  y = in @ [Wl;Wr]^T + [bl;br] -------------
template<int COLG, int ROWG>
__global__ __launch_bounds__(COLG * ROWG, 1)
void gemm_dual(const float* __restrict__ in, int N,
               const float* __restrict__ Wl, const float* __restrict__ bl,
               const float* __restrict__ Wr, const float* __restrict__ br,
               int Jhalf,
               float* __restrict__ xl, float* __restrict__ xr)
{
    constexpr int J     = COLG * 8;
    constexpr int RPT   = ROWG * 8;
    constexpr int XSPAD = 132;
    extern __shared__ float sm[];
    float* Wt   = sm;                   // [128][J]  k-major
    float* bcol = Wt + 128 * J;         // [J]
    float* xs   = bcol + J;             // [RPT][XSPAD]

    const int tid = threadIdx.x;
    const int nth = blockDim.x;

    for (int idx = tid; idx < 128 * J; idx += nth) {
        int k = idx / J, j = idx % J;
        Wt[idx] = (j < Jhalf) ? Wl[j * 128 + k] : Wr[(j - Jhalf) * 128 + k];
    }
    for (int j = tid; j < J; j += nth)
        bcol[j] = (j < Jhalf) ? bl[j] : br[j - Jhalf];
    __syncthreads();

    const int cg = tid % COLG;
    const int rg = tid / COLG;
    const int ntiles = (N + RPT - 1) / RPT;
    const float4* in4 = reinterpret_cast<const float4*>(in);

    for (int tile = blockIdx.x; tile < ntiles; tile += gridDim.x) {
        const int r0 = tile * RPT;
        for (int idx = tid; idx < RPT * 32; idx += nth) {
            int r = idx >> 5, k4 = idx & 31;
            int row = r0 + r;
            float4 v = (row < N) ? in4[(size_t)row * 32 + k4]
                                 : make_float4(0.f, 0.f, 0.f, 0.f);
            *reinterpret_cast<float4*>(xs + r * XSPAD + k4 * 4) = v;
        }
        __syncthreads();

        float acc[8][8];
        #pragma unroll
        for (int r = 0; r < 8; r++)
            #pragma unroll
            for (int c = 0; c < 8; c++) acc[r][c] = 0.f;

        const float* xsb = xs + (rg * 8) * XSPAD;
        const float* wb  = Wt + cg * 8;
        #pragma unroll 2
        for (int k = 0; k < 128; k++) {
            float4 w0 = *reinterpret_cast<const float4*>(wb + k * J);
            float4 w1 = *reinterpret_cast<const float4*>(wb + k * J + 4);
            #pragma unroll
            for (int r = 0; r < 8; r++) {
                float xv = xsb[r * XSPAD + k];
                acc[r][0] += w0.x * xv; acc[r][1] += w0.y * xv;
                acc[r][2] += w0.z * xv; acc[r][3] += w0.w * xv;
                acc[r][4] += w1.x * xv; acc[r][5] += w1.y * xv;
                acc[r][6] += w1.z * xv; acc[r][7] += w1.w * xv;
            }
        }

        const int j0 = cg * 8;
        float4 bv0 = *reinterpret_cast<const float4*>(bcol + j0);
        float4 bv1 = *reinterpret_cast<const float4*>(bcol + j0 + 4);
        float* outbase; int jo;
        if (j0 < Jhalf) { outbase = xl; jo = j0; }
        else            { outbase = xr; jo = j0 - Jhalf; }

        #pragma unroll
        for (int r = 0; r < 8; r++) {
            int row = r0 + rg * 8 + r;
            if (row < N) {
                float* op = outbase + (size_t)row * Jhalf + jo;
                *reinterpret_cast<float4*>(op) =
                    make_float4(acc[r][0] + bv0.x, acc[r][1] + bv0.y,
                                acc[r][2] + bv0.z, acc[r][3] + bv0.w);
                *reinterpret_cast<float4*>(op + 4) =
                    make_float4(acc[r][4] + bv1.x, acc[r][5] + bv1.y,
                                acc[r][6] + bv1.z, acc[r][7] + bv1.w);
            }
        }
        __syncthreads();
    }
}

// ---- fused edge pass, H=4, C=32: score -> exp -> scatter exp*xl, sum exp ----
// 2 edges per warp. acc[dst] += exp(s)*xl[src]; sum[dst] += exp(s).
__global__ void edge_h4(const float* __restrict__ xl, const float* __restrict__ xr,
                        const int* __restrict__ ei, int E, int ET,
                        const float* __restrict__ att,
                        float* __restrict__ acc, float* __restrict__ sumb)
{
    unsigned gw = (blockIdx.x * (unsigned)blockDim.x + threadIdx.x) >> 5;
    int e0 = (int)(gw * 2);
    if (e0 >= ET) return;
    int e1 = e0 + 1;
    int lane = threadIdx.x & 31;
    int h = lane >> 3;

    int s0, d0;
    if (e0 < E) { s0 = ei[e0]; d0 = ei[E + e0]; } else { s0 = d0 = e0 - E; }
    bool has1 = (e1 < ET);
    int s1 = 0, d1 = 0;
    if (has1) { if (e1 < E) { s1 = ei[e1]; d1 = ei[E + e1]; } else { s1 = d1 = e1 - E; } }

    float4 av = *reinterpret_cast<const float4*>(att + lane * 4);
    float4 a0 = *reinterpret_cast<const float4*>(xl + (size_t)s0 * 128 + lane * 4);
    float4 b0 = *reinterpret_cast<const float4*>(xr + (size_t)d0 * 128 + lane * 4);

    float p0 = lrelu(a0.x + b0.x) * av.x + lrelu(a0.y + b0.y) * av.y
             + lrelu(a0.z + b0.z) * av.z + lrelu(a0.w + b0.w) * av.w;

    float4 a1 = make_float4(0.f, 0.f, 0.f, 0.f);
    float p1 = 0.f;
    if (has1) {
        a1 = *reinterpret_cast<const float4*>(xl + (size_t)s1 * 128 + lane * 4);
        float4 b1 = *reinterpret_cast<const float4*>(xr + (size_t)d1 * 128 + lane * 4);
        p1 = lrelu(a1.x + b1.x) * av.x + lrelu(a1.y + b1.y) * av.y
           + lrelu(a1.z + b1.z) * av.z + lrelu(a1.w + b1.w) * av.w;
    }

    #pragma unroll
    for (int o = 1; o < 8; o <<= 1) {
        p0 += __shfl_xor_sync(0xffffffffu, p0, o);
        p1 += __shfl_xor_sync(0xffffffffu, p1, o);
    }
    float q0 = __expf(p0);
    a0.x *= q0; a0.y *= q0; a0.z *= q0; a0.w *= q0;
    red_add_v4(acc + (size_t)d0 * 128 + lane * 4, a0);
    if ((lane & 7) == 0) atomicAdd(&sumb[(size_t)d0 * 4 + h], q0);
    if (has1) {
        float q1 = __expf(p1);
        a1.x *= q1; a1.y *= q1; a1.z *= q1; a1.w *= q1;
        red_add_v4(acc + (size_t)d1 * 128 + lane * 4, a1);
        if ((lane & 7) == 0) atomicAdd(&sumb[(size_t)d1 * 4 + h], q1);
    }
}

// ---- fused edge pass, H=1, C=40 (2 edges per warp, 16-lane halves) ----------
__global__ void edge_h1(const float* __restrict__ xl, const float* __restrict__ xr,
                        const int* __restrict__ ei, int E, int ET,
                        const float* __restrict__ att,
                        float* __restrict__ acc, float* __restrict__ sumb)
{
    unsigned gw = (blockIdx.x * (unsigned)blockDim.x + threadIdx.x) >> 5;
    int lane = threadIdx.x & 31;
    int grp  = lane >> 4;
    int gl   = lane & 15;
    int e = (int)(gw * 2) + grp;
    bool valid = (e < ET);
    int src = 0, dst = 0;
    if (valid) { if (e < E) { src = ei[e]; dst = ei[E + e]; } else { src = dst = e - E; } }

    float p = 0.f;
    float4 a = make_float4(0.f, 0.f, 0.f, 0.f);
    if (valid && gl < 10) {
        a = *reinterpret_cast<const float4*>(xl + (size_t)src * 40 + gl * 4);
        float4 b = *reinterpret_cast<const float4*>(xr + (size_t)dst * 40 + gl * 4);
        float4 t = *reinterpret_cast<const float4*>(att + gl * 4);
        p = lrelu(a.x + b.x) * t.x + lrelu(a.y + b.y) * t.y
          + lrelu(a.z + b.z) * t.z + lrelu(a.w + b.w) * t.w;
    }
    #pragma unroll
    for (int o = 8; o >= 1; o >>= 1)
        p += __shfl_xor_sync(0xffffffffu, p, o);
    if (valid && gl < 10) {
        float q = __expf(p);
        a.x *= q; a.y *= q; a.z *= q; a.w *= q;
        red_add_v4(acc + (size_t)dst * 40 + gl * 4, a);
        if (gl == 0) atomicAdd(&sumb[dst], q);
    }
}

// ---------------- epilogues: divide by sum, add bias, (ELU) ------------------
__global__ void div_bias_elu4(const float4* __restrict__ in, const float* __restrict__ sumb,
                              const float4* __restrict__ bias, float4* __restrict__ out,
                              int total4)
{
    int i = blockIdx.x * blockDim.x + threadIdx.x;
    if (i >= total4) return;
    int n = i >> 5, c = i & 31;
    float inv = 1.f / __ldg(&sumb[n * 4 + (c >> 3)]);
    float4 v = in[i], b = bias[c];
    v.x = v.x * inv + b.x; v.y = v.y * inv + b.y;
    v.z = v.z * inv + b.z; v.w = v.w * inv + b.w;
    v.x = v.x > 0.f ? v.x : expm1f(v.x);
    v.y = v.y > 0.f ? v.y : expm1f(v.y);
    v.z = v.z > 0.f ? v.z : expm1f(v.z);
    v.w = v.w > 0.f ? v.w : expm1f(v.w);
    out[i] = v;
}

__global__ void div_bias40_4(const float4* __restrict__ in, const float* __restrict__ sumb,
                             const float4* __restrict__ bias, float4* __restrict__ out,
                             int total4)
{
    int i = blockIdx.x * blockDim.x + threadIdx.x;
    if (i >= total4) return;
    int n = i / 10, c = i % 10;
    float inv = 1.f / __ldg(&sumb[n]);
    float4 v = in[i], b = bias[c];
    v.x = v.x * inv + b.x; v.y = v.y * inv + b.y;
    v.z = v.z * inv + b.z; v.w = v.w * inv + b.w;
    out[i] = v;
}

// ---------------- host orchestration ----------------------------------------
static inline int ceil_div(int a, int b) { return (a + b - 1) / b; }

extern "C" void kernel_launch(void* const* d_in, const int* in_sizes, int n_in,
                              void* d_out, int out_size)
{
    const float* x   = (const float*)d_in[0];
    const int*   ei  = (const int*)  d_in[1];
    const float* W1l = (const float*)d_in[2];
    const float* b1l = (const float*)d_in[3];
    const float* W1r = (const float*)d_in[4];
    const float* b1r = (const float*)d_in[5];
    const float* at1 = (const float*)d_in[6];
    const float* bs1 = (const float*)d_in[7];
    const float* W2l = (const float*)d_in[8];
    const float* b2l = (const float*)d_in[9];
    const float* W2r = (const float*)d_in[10];
    const float* b2r = (const float*)d_in[11];
    const float* at2 = (const float*)d_in[12];
    const float* bs2 = (const float*)d_in[13];
    const float* W3l = (const float*)d_in[14];
    const float* b3l = (const float*)d_in[15];
    const float* W3r = (const float*)d_in[16];
    const float* b3r = (const float*)d_in[17];
    const float* at3 = (const float*)d_in[18];
    const float* bs3 = (const float*)d_in[19];
    float* out = (float*)d_out;

    const int N  = in_sizes[0] / 128;
    const int E  = in_sizes[1] / 2;
    const int ET = E + N;

    float *xl, *xr, *h, *acc, *sum;
    cudaGetSymbolAddress((void**)&xl,  g_xl);
    cudaGetSymbolAddress((void**)&xr,  g_xr);
    cudaGetSymbolAddress((void**)&h,   g_h);
    cudaGetSymbolAddress((void**)&acc, g_acc);
    cudaGetSymbolAddress((void**)&sum, g_sum);

    const int SM12 = (128 * 256 + 256 + 64 * 132) * 4;   // 165888 B
    const int SM3  = (128 * 80 + 80 + 128 * 132) * 4;    // 108864 B
    cudaFuncSetAttribute(gemm_dual<32, 8>,  cudaFuncAttributeMaxDynamicSharedMemorySize, SM12);
    cudaFuncSetAttribute(gemm_dual<10, 16>, cudaFuncAttributeMaxDynamicSharedMemorySize, SM3);

    const int edgeBlocks = ceil_div(ET, 16);   // 2 edges/warp, 8 warps/block

    // ===== layer 1 (H=4, C=32) =====
    gemm_dual<32, 8><<<148, 256, SM12>>>(x, N, W1l, b1l, W1r, b1r, 128, xl, xr);
    cudaMemsetAsync(sum, 0, (size_t)N * 4 * sizeof(float));
    cudaMemsetAsync(acc, 0, (size_t)N * 128 * sizeof(float));
    edge_h4<<<edgeBlocks, 256>>>(xl, xr, ei, E, ET, at1, acc, sum);
    div_bias_elu4<<<ceil_div(N * 32, 256), 256>>>((const float4*)acc, sum,
                                                  (const float4*)bs1, (float4*)h, N * 32);

    // ===== layer 2 (H=4, C=32) =====
    gemm_dual<32, 8><<<148, 256, SM12>>>(h, N, W2l, b2l, W2r, b2r, 128, xl, xr);
    cudaMemsetAsync(sum, 0, (size_t)N * 4 * sizeof(float));
    cudaMemsetAsync(acc, 0, (size_t)N * 128 * sizeof(float));
    edge_h4<<<edgeBlocks, 256>>>(xl, xr, ei, E, ET, at2, acc, sum);
    div_bias_elu4<<<ceil_div(N * 32, 256), 256>>>((const float4*)acc, sum,
                                                  (const float4*)bs2, (float4*)h, N * 32);

    // ===== layer 3 (H=1, C=40) =====
    gemm_dual<10, 16><<<148, 160, SM3>>>(h, N, W3l, b3l, W3r, b3r, 40, xl, xr);
    cudaMemsetAsync(sum, 0, (size_t)N * sizeof(float));
    cudaMemsetAsync(acc, 0, (size_t)N * 40 * sizeof(float));
    edge_h1<<<edgeBlocks, 256>>>(xl, xr, ei, E, ET, at3, acc, sum);
    div_bias40_4<<<ceil_div(N * 10, 256), 256>>>((const float4*)acc, sum,
                                                 (const float4*)bs3, (float4*)out, N * 10);
}

// round 7
// speedup vs baseline: 1.7792x; 1.0587x over previous
#include <cuda_runtime.h>
#include <cstdint>

#define NMAX 100000
#define EMAX 1000000
#define ETMAX (EMAX + NMAX)

// ---------------- scratch (device globals: allocation-free rule) -------------
__device__ float g_xl[(size_t)NMAX * 128];
__device__ float g_xr[(size_t)NMAX * 128];
__device__ float g_h [(size_t)NMAX * 128];
__device__ float g_acc[(size_t)NMAX * 128];
__device__ float g_sum[(size_t)NMAX * 4];

// ---------------- helpers ----------------------------------------------------
typedef unsigned long long u64;

__device__ __forceinline__ float lrelu(float v) { return v > 0.f ? v : 0.2f * v; }

__device__ __forceinline__ void red_add_v4(float* p, float4 v) {
    asm volatile("red.global.add.v4.f32 [%0], {%1,%2,%3,%4};"
                 :: "l"(p), "f"(v.x), "f"(v.y), "f"(v.z), "f"(v.w) : "memory");
}

__device__ __forceinline__ u64 pack_dup(float x) {
    u64 r; asm("mov.b64 %0, {%1, %1};" : "=l"(r) : "f"(x)); return r;
}
__device__ __forceinline__ void ffma2(u64& d, u64 a, u64 b) {
    asm("fma.rn.f32x2 %0, %1, %2, %0;" : "+l"(d) : "l"(a), "l"(b));
}
__device__ __forceinline__ float2 unpack2(u64 v) {
    float2 f; asm("mov.b64 {%0, %1}, %2;" : "=f"(f.x), "=f"(f.y) : "l"(v)); return f;
}
__device__ __forceinline__ u64 d2l(double d) { return __double_as_longlong(d); }

// ---------------- fused dual GEMM:  y = in @ [Wl;Wr]^T + [bl;br] -------------
// f32x2 packed-FMA inner loop: each thread owns an 8-row x 8-col tile held as
// 8x4 b64 accumulators (column pairs). W pairs load directly as double2 (free).
template<int COLG, int ROWG>
__global__ __launch_bounds__(COLG * ROWG, 1)
void gemm_dual(const float* __restrict__ in, int N,
               const float* __restrict__ Wl, const float* __restrict__ bl,
               const float* __restrict__ Wr, const float* __restrict__ br,
               int Jhalf,
               float* __restrict__ xl, float* __restrict__ xr)
{
    constexpr int J     = COLG * 8;
    constexpr int RPT   = ROWG * 8;
    constexpr int XSPAD = 132;          // 132*4 = 528 B (16B-aligned rows)
    extern __shared__ float sm[];
    float* Wt   = sm;                   // [128][J]  k-major
    float* bcol = Wt + 128 * J;         // [J]
    float* xs   = bcol + J;             // [RPT][XSPAD]

    const int tid = threadIdx.x;
    const int nth = blockDim.x;

    for (int idx = tid; idx < 128 * J; idx += nth) {
        int k = idx / J, j = idx % J;
        Wt[idx] = (j < Jhalf) ? Wl[j * 128 + k] : Wr[(j - Jhalf) * 128 + k];
    }
    for (int j = tid; j < J; j += nth)
        bcol[j] = (j < Jhalf) ? bl[j] : br[j - Jhalf];
    __syncthreads();

    const int cg = tid % COLG;
    const int rg = tid / COLG;
    const int ntiles = (N + RPT - 1) / RPT;
    const float4* in4 = reinterpret_cast<const float4*>(in);

    for (int tile = blockIdx.x; tile < ntiles; tile += gridDim.x) {
        const int r0 = tile * RPT;
        for (int idx = tid; idx < RPT * 32; idx += nth) {
            int r = idx >> 5, k4 = idx & 31;
            int row = r0 + r;
            float4 v = (row < N) ? in4[(size_t)row * 32 + k4]
                                 : make_float4(0.f, 0.f, 0.f, 0.f);
            *reinterpret_cast<float4*>(xs + r * XSPAD + k4 * 4) = v;
        }
        __syncthreads();

        u64 acc2[8][4];
        #pragma unroll
        for (int r = 0; r < 8; r++)
            #pragma unroll
            for (int c = 0; c < 4; c++) acc2[r][c] = 0ull;   // bits of (+0f,+0f)

        const float* xsb = xs + (rg * 8) * XSPAD;
        const float* wb  = Wt + cg * 8;

        for (int k = 0; k < 128; k += 4) {
            float4 xv[8];
            #pragma unroll
            for (int r = 0; r < 8; r++)
                xv[r] = *reinterpret_cast<const float4*>(xsb + r * XSPAD + k);
            #pragma unroll
            for (int kk = 0; kk < 4; kk++) {
                const float* wrow = wb + (k + kk) * J;
                double2 wA = *reinterpret_cast<const double2*>(wrow);
                double2 wB = *reinterpret_cast<const double2*>(wrow + 4);
                u64 w0 = d2l(wA.x), w1 = d2l(wA.y);
                u64 w2 = d2l(wB.x), w3 = d2l(wB.y);
                #pragma unroll
                for (int r = 0; r < 8; r++) {
                    float xk = (kk == 0) ? xv[r].x : (kk == 1) ? xv[r].y
                             : (kk == 2) ? xv[r].z : xv[r].w;
                    u64 xx = pack_dup(xk);
                    ffma2(acc2[r][0], w0, xx);
                    ffma2(acc2[r][1], w1, xx);
                    ffma2(acc2[r][2], w2, xx);
                    ffma2(acc2[r][3], w3, xx);
                }
            }
        }

        const int j0 = cg * 8;
        float4 bv0 = *reinterpret_cast<const float4*>(bcol + j0);
        float4 bv1 = *reinterpret_cast<const float4*>(bcol + j0 + 4);
        float* outbase; int jo;
        if (j0 < Jhalf) { outbase = xl; jo = j0; }
        else            { outbase = xr; jo = j0 - Jhalf; }

        #pragma unroll
        for (int r = 0; r < 8; r++) {
            int row = r0 + rg * 8 + r;
            if (row < N) {
                float2 c0 = unpack2(acc2[r][0]);
                float2 c1 = unpack2(acc2[r][1]);
                float2 c2 = unpack2(acc2[r][2]);
                float2 c3 = unpack2(acc2[r][3]);
                float* op = outbase + (size_t)row * Jhalf + jo;
                *reinterpret_cast<float4*>(op) =
                    make_float4(c0.x + bv0.x, c0.y + bv0.y, c1.x + bv0.z, c1.y + bv0.w);
                *reinterpret_cast<float4*>(op + 4) =
                    make_float4(c2.x + bv1.x, c2.y + bv1.y, c3.x + bv1.z, c3.y + bv1.w);
            }
        }
        __syncthreads();
    }
}

// ---- fused edge pass, H=4, C=32 (4 edges per warp) -------------------------
// acc[dst] += exp(s)*xl[src]; sum[dst] += exp(s).
__global__ void edge_h4(const float* __restrict__ xl, const float* __restrict__ xr,
                        const int* __restrict__ ei, int E, int ET,
                        const float* __restrict__ att,
                        float* __restrict__ acc, float* __restrict__ sumb)
{
    unsigned gw = (blockIdx.x * (unsigned)blockDim.x + threadIdx.x) >> 5;
    int base = (int)(gw * 4);
    if (base >= ET) return;
    int lane = threadIdx.x & 31;
    int h = lane >> 3;
    float4 av = *reinterpret_cast<const float4*>(att + lane * 4);

    int sv[4], dv[4]; bool ok[4];
    #pragma unroll
    for (int j = 0; j < 4; j++) {
        int e = base + j;
        ok[j] = (e < ET);
        int ec = ok[j] ? e : 0;
        if (ec < E) { sv[j] = ei[ec]; dv[j] = ei[E + ec]; }
        else        { sv[j] = dv[j] = ec - E; }
    }

    float4 a[4]; float p[4];
    #pragma unroll
    for (int j = 0; j < 4; j++) {
        a[j] = *reinterpret_cast<const float4*>(xl + (size_t)sv[j] * 128 + lane * 4);
        float4 b = *reinterpret_cast<const float4*>(xr + (size_t)dv[j] * 128 + lane * 4);
        p[j] = lrelu(a[j].x + b.x) * av.x + lrelu(a[j].y + b.y) * av.y
             + lrelu(a[j].z + b.z) * av.z + lrelu(a[j].w + b.w) * av.w;
    }
    #pragma unroll
    for (int o = 1; o < 8; o <<= 1) {
        #pragma unroll
        for (int j = 0; j < 4; j++)
            p[j] += __shfl_xor_sync(0xffffffffu, p[j], o);
    }
    #pragma unroll
    for (int j = 0; j < 4; j++) {
        if (ok[j]) {
            float q = __expf(p[j]);
            float4 v = a[j];
            v.x *= q; v.y *= q; v.z *= q; v.w *= q;
            red_add_v4(acc + (size_t)dv[j] * 128 + lane * 4, v);
            if ((lane & 7) == 0) atomicAdd(&sumb[(size_t)dv[j] * 4 + h], q);
        }
    }
}

// ---- fused edge pass, H=1, C=40 (4 edges per warp: 2 x 16-lane groups x2) --
__global__ void edge_h1(const float* __restrict__ xl, const float* __restrict__ xr,
                        const int* __restrict__ ei, int E, int ET,
                        const float* __restrict__ att,
                        float* __restrict__ acc, float* __restrict__ sumb)
{
    unsigned gw = (blockIdx.x * (unsigned)blockDim.x + threadIdx.x) >> 5;
    int lane = threadIdx.x & 31;
    int grp  = lane >> 4;
    int gl   = lane & 15;
    int base = (int)(gw * 4) + grp;
    float4 t = make_float4(0.f, 0.f, 0.f, 0.f);
    if (gl < 10) t = *reinterpret_cast<const float4*>(att + gl * 4);

    #pragma unroll
    for (int j = 0; j < 2; j++) {
        int e = base + 2 * j;
        bool valid = (e < ET);
        int ec = valid ? e : 0;
        int src, dst;
        if (ec < E) { src = ei[ec]; dst = ei[E + ec]; } else { src = dst = ec - E; }

        float p = 0.f;
        float4 a = make_float4(0.f, 0.f, 0.f, 0.f);
        if (gl < 10) {
            a = *reinterpret_cast<const float4*>(xl + (size_t)src * 40 + gl * 4);
            float4 b = *reinterpret_cast<const float4*>(xr + (size_t)dst * 40 + gl * 4);
            p = lrelu(a.x + b.x) * t.x + lrelu(a.y + b.y) * t.y
              + lrelu(a.z + b.z) * t.z + lrelu(a.w + b.w) * t.w;
        }
        #pragma unroll
        for (int o = 8; o >= 1; o >>= 1)
            p += __shfl_xor_sync(0xffffffffu, p, o);
        if (valid && gl < 10) {
            float q = __expf(p);
            a.x *= q; a.y *= q; a.z *= q; a.w *= q;
            red_add_v4(acc + (size_t)dst * 40 + gl * 4, a);
            if (gl == 0) atomicAdd(&sumb[dst], q);
        }
    }
}

// ---------------- epilogues: divide by sum, add bias, (ELU) ------------------
__global__ void div_bias_elu4(const float4* __restrict__ in, const float* __restrict__ sumb,
                              const float4* __restrict__ bias, float4* __restrict__ out,
                              int total4)
{
    int i = blockIdx.x * blockDim.x + threadIdx.x;
    if (i >= total4) return;
    int n = i >> 5, c = i & 31;
    float inv = 1.f / __ldg(&sumb[n * 4 + (c >> 3)]);
    float4 v = in[i], b = bias[c];
    v.x = v.x * inv + b.x; v.y = v.y * inv + b.y;
    v.z = v.z * inv + b.z; v.w = v.w * inv + b.w;
    v.x = v.x > 0.f ? v.x : expm1f(v.x);
    v.y = v.y > 0.f ? v.y : expm1f(v.y);
    v.z = v.z > 0.f ? v.z : expm1f(v.z);
    v.w = v.w > 0.f ? v.w : expm1f(v.w);
    out[i] = v;
}

__global__ void div_bias40_4(const float4* __restrict__ in, const float* __restrict__ sumb,
                             const float4* __restrict__ bias, float4* __restrict__ out,
                             int total4)
{
    int i = blockIdx.x * blockDim.x + threadIdx.x;
    if (i >= total4) return;
    int n = i / 10, c = i % 10;
    float inv = 1.f / __ldg(&sumb[n]);
    float4 v = in[i], b = bias[c];
    v.x = v.x * inv + b.x; v.y = v.y * inv + b.y;
    v.z = v.z * inv + b.z; v.w = v.w * inv + b.w;
    out[i] = v;
}

// ---------------- host orchestration ----------------------------------------
static inline int ceil_div(int a, int b) { return (a + b - 1) / b; }

extern "C" void kernel_launch(void* const* d_in, const int* in_sizes, int n_in,
                              void* d_out, int out_size)
{
    const float* x   = (const float*)d_in[0];
    const int*   ei  = (const int*)  d_in[1];
    const float* W1l = (const float*)d_in[2];
    const float* b1l = (const float*)d_in[3];
    const float* W1r = (const float*)d_in[4];
    const float* b1r = (const float*)d_in[5];
    const float* at1 = (const float*)d_in[6];
    const float* bs1 = (const float*)d_in[7];
    const float* W2l = (const float*)d_in[8];
    const float* b2l = (const float*)d_in[9];
    const float* W2r = (const float*)d_in[10];
    const float* b2r = (const float*)d_in[11];
    const float* at2 = (const float*)d_in[12];
    const float* bs2 = (const float*)d_in[13];
    const float* W3l = (const float*)d_in[14];
    const float* b3l = (const float*)d_in[15];
    const float* W3r = (const float*)d_in[16];
    const float* b3r = (const float*)d_in[17];
    const float* at3 = (const float*)d_in[18];
    const float* bs3 = (const float*)d_in[19];
    float* out = (float*)d_out;

    const int N  = in_sizes[0] / 128;
    const int E  = in_sizes[1] / 2;
    const int ET = E + N;

    float *xl, *xr, *h, *acc, *sum;
    cudaGetSymbolAddress((void**)&xl,  g_xl);
    cudaGetSymbolAddress((void**)&xr,  g_xr);
    cudaGetSymbolAddress((void**)&h,   g_h);
    cudaGetSymbolAddress((void**)&acc, g_acc);
    cudaGetSymbolAddress((void**)&sum, g_sum);

    const int SM12 = (128 * 256 + 256 + 64 * 132) * 4;   // 165888 B
    const int SM3  = (128 * 80 + 80 + 128 * 132) * 4;    // 108864 B
    cudaFuncSetAttribute(gemm_dual<32, 8>,  cudaFuncAttributeMaxDynamicSharedMemorySize, SM12);
    cudaFuncSetAttribute(gemm_dual<10, 16>, cudaFuncAttributeMaxDynamicSharedMemorySize, SM3);

    const int edgeBlocks = ceil_div(ET, 32);   // 4 edges/warp, 8 warps/block

    // ===== layer 1 (H=4, C=32) =====
    gemm_dual<32, 8><<<148, 256, SM12>>>(x, N, W1l, b1l, W1r, b1r, 128, xl, xr);
    cudaMemsetAsync(sum, 0, (size_t)N * 4 * sizeof(float));
    cudaMemsetAsync(acc, 0, (size_t)N * 128 * sizeof(float));
    edge_h4<<<edgeBlocks, 256>>>(xl, xr, ei, E, ET, at1, acc, sum);
    div_bias_elu4<<<ceil_div(N * 32, 256), 256>>>((const float4*)acc, sum,
                                                  (const float4*)bs1, (float4*)h, N * 32);

    // ===== layer 2 (H=4, C=32) =====
    gemm_dual<32, 8><<<148, 256, SM12>>>(h, N, W2l, b2l, W2r, b2r, 128, xl, xr);
    cudaMemsetAsync(sum, 0, (size_t)N * 4 * sizeof(float));
    cudaMemsetAsync(acc, 0, (size_t)N * 128 * sizeof(float));
    edge_h4<<<edgeBlocks, 256>>>(xl, xr, ei, E, ET, at2, acc, sum);
    div_bias_elu4<<<ceil_div(N * 32, 256), 256>>>((const float4*)acc, sum,
                                                  (const float4*)bs2, (float4*)h, N * 32);

    // ===== layer 3 (H=1, C=40) =====
    gemm_dual<10, 16><<<148, 160, SM3>>>(h, N, W3l, b3l, W3r, b3r, 40, xl, xr);
    cudaMemsetAsync(sum, 0, (size_t)N * sizeof(float));
    cudaMemsetAsync(acc, 0, (size_t)N * 40 * sizeof(float));
    edge_h1<<<edgeBlocks, 256>>>(xl, xr, ei, E, ET, at3, acc, sum);
    div_bias40_4<<<ceil_div(N * 10, 256), 256>>>((const float4*)acc, sum,
                                                 (const float4*)bs3, (float4*)out, N * 10);
}

// round 10
// speedup vs baseline: 1.8247x; 1.0256x over previous
#include <cuda_runtime.h>
#include <cstdint>

#define NMAX 100000
#define EMAX 1000000
#define ETMAX (EMAX + NMAX)

// ---------------- scratch (device globals: allocation-free rule) -------------
__device__ float g_xl[(size_t)NMAX * 128];
__device__ float g_xr[(size_t)NMAX * 128];
__device__ float g_h [(size_t)NMAX * 128];
__device__ float g_acc[(size_t)NMAX * 128];
__device__ float g_sum[(size_t)NMAX * 4];

// ---------------- helpers ----------------------------------------------------
typedef unsigned long long u64;

__device__ __forceinline__ float lrelu(float v) { return v > 0.f ? v : 0.2f * v; }

__device__ __forceinline__ void red_add_v4(float* p, float4 v) {
    asm volatile("red.global.add.v4.f32 [%0], {%1,%2,%3,%4};"
                 :: "l"(p), "f"(v.x), "f"(v.y), "f"(v.z), "f"(v.w) : "memory");
}

__device__ __forceinline__ u64 pack_dup(float x) {
    u64 r; asm("mov.b64 %0, {%1, %1};" : "=l"(r) : "f"(x)); return r;
}
__device__ __forceinline__ void ffma2(u64& d, u64 a, u64 b) {
    asm("fma.rn.f32x2 %0, %1, %2, %0;" : "+l"(d) : "l"(a), "l"(b));
}
__device__ __forceinline__ float2 unpack2(u64 v) {
    float2 f; asm("mov.b64 {%0, %1}, %2;" : "=f"(f.x), "=f"(f.y) : "l"(v)); return f;
}
__device__ __forceinline__ u64 d2l(double d) { return __double_as_longlong(d); }

// ---------------- fused dual GEMM, column-split + K-chunked ------------------
// Block handles JB = COLG*8 output cols starting at blockIdx.y*JB.
// K (=128) processed in chunks of KC=32 so the x tile stays small -> multi-CTA
// occupancy. Each thread: 8 rows x 8 cols via f32x2 packed FMA.
template<int COLG, int ROWG, int MAXCTA>
__global__ __launch_bounds__(COLG * ROWG, MAXCTA)
void gemm_dual(const float* __restrict__ in, int N,
               const float* __restrict__ Wl, const float* __restrict__ bl,
               const float* __restrict__ Wr, const float* __restrict__ br,
               int Jhalf,
               float* __restrict__ xl, float* __restrict__ xr)
{
    constexpr int JB    = COLG * 8;
    constexpr int RPT   = ROWG * 8;
    constexpr int KC    = 32;
    constexpr int XS    = KC + 4;       // 36 floats/row, 16B-aligned
    extern __shared__ float sm[];
    float* Wt   = sm;                   // [128][JB]  k-major
    float* bcol = Wt + 128 * JB;        // [JB]
    float* xs   = bcol + JB;            // [RPT][XS]

    const int tid    = threadIdx.x;
    const int nth    = blockDim.x;
    const int coloff = blockIdx.y * JB;

    for (int idx = tid; idx < 128 * JB; idx += nth) {
        int k = idx / JB, jl = idx % JB;
        int j = coloff + jl;
        Wt[idx] = (j < Jhalf) ? Wl[j * 128 + k] : Wr[(j - Jhalf) * 128 + k];
    }
    for (int jl = tid; jl < JB; jl += nth) {
        int j = coloff + jl;
        bcol[jl] = (j < Jhalf) ? bl[j] : br[j - Jhalf];
    }
    __syncthreads();

    const int cg = tid % COLG;
    const int rg = tid / COLG;
    const int ntiles = (N + RPT - 1) / RPT;
    const float4* in4 = reinterpret_cast<const float4*>(in);

    for (int tile = blockIdx.x; tile < ntiles; tile += gridDim.x) {
        const int r0 = tile * RPT;

        u64 acc2[8][4];
        #pragma unroll
        for (int r = 0; r < 8; r++)
            #pragma unroll
            for (int c = 0; c < 4; c++) acc2[r][c] = 0ull;

        const float* xsb = xs + (rg * 8) * XS;
        const float* wb  = Wt + cg * 8;

        #pragma unroll
        for (int ch = 0; ch < 128 / KC; ch++) {
            // stage x chunk: RPT rows x KC k's
            for (int idx = tid; idx < RPT * (KC / 4); idx += nth) {
                int r = idx / (KC / 4), q = idx % (KC / 4);
                int row = r0 + r;
                float4 v = (row < N) ? in4[(size_t)row * 32 + ch * (KC / 4) + q]
                                     : make_float4(0.f, 0.f, 0.f, 0.f);
                *reinterpret_cast<float4*>(xs + r * XS + q * 4) = v;
            }
            __syncthreads();

            const float* wch = wb + (ch * KC) * JB;
            for (int k = 0; k < KC; k += 4) {
                float4 xv[8];
                #pragma unroll
                for (int r = 0; r < 8; r++)
                    xv[r] = *reinterpret_cast<const float4*>(xsb + r * XS + k);
                #pragma unroll
                for (int kk = 0; kk < 4; kk++) {
                    const float* wrow = wch + (k + kk) * JB;
                    double2 wA = *reinterpret_cast<const double2*>(wrow);
                    double2 wB = *reinterpret_cast<const double2*>(wrow + 4);
                    u64 w0 = d2l(wA.x), w1 = d2l(wA.y);
                    u64 w2 = d2l(wB.x), w3 = d2l(wB.y);
                    #pragma unroll
                    for (int r = 0; r < 8; r++) {
                        float xk = (kk == 0) ? xv[r].x : (kk == 1) ? xv[r].y
                                 : (kk == 2) ? xv[r].z : xv[r].w;
                        u64 xx = pack_dup(xk);
                        ffma2(acc2[r][0], w0, xx);
                        ffma2(acc2[r][1], w1, xx);
                        ffma2(acc2[r][2], w2, xx);
                        ffma2(acc2[r][3], w3, xx);
                    }
                }
            }
            __syncthreads();
        }

        const int jl0 = cg * 8;
        const int j0  = coloff + jl0;
        float4 bv0 = *reinterpret_cast<const float4*>(bcol + jl0);
        float4 bv1 = *reinterpret_cast<const float4*>(bcol + jl0 + 4);
        float* outbase; int jo;
        if (j0 < Jhalf) { outbase = xl; jo = j0; }
        else            { outbase = xr; jo = j0 - Jhalf; }

        #pragma unroll
        for (int r = 0; r < 8; r++) {
            int row = r0 + rg * 8 + r;
            if (row < N) {
                float2 c0 = unpack2(acc2[r][0]);
                float2 c1 = unpack2(acc2[r][1]);
                float2 c2 = unpack2(acc2[r][2]);
                float2 c3 = unpack2(acc2[r][3]);
                float* op = outbase + (size_t)row * Jhalf + jo;
                *reinterpret_cast<float4*>(op) =
                    make_float4(c0.x + bv0.x, c0.y + bv0.y, c1.x + bv0.z, c1.y + bv0.w);
                *reinterpret_cast<float4*>(op + 4) =
                    make_float4(c2.x + bv1.x, c2.y + bv1.y, c3.x + bv1.z, c3.y + bv1.w);
            }
        }
    }
}

// ---- fused edge pass, H=4, C=32 (4 edges per warp) -------------------------
__global__ void edge_h4(const float* __restrict__ xl, const float* __restrict__ xr,
                        const int* __restrict__ ei, int E, int ET,
                        const float* __restrict__ att,
                        float* __restrict__ acc, float* __restrict__ sumb)
{
    unsigned gw = (blockIdx.x * (unsigned)blockDim.x + threadIdx.x) >> 5;
    int base = (int)(gw * 4);
    if (base >= ET) return;
    int lane = threadIdx.x & 31;
    int h = lane >> 3;
    float4 av = *reinterpret_cast<const float4*>(att + lane * 4);

    int sv[4], dv[4]; bool ok[4];
    #pragma unroll
    for (int j = 0; j < 4; j++) {
        int e = base + j;
        ok[j] = (e < ET);
        int ec = ok[j] ? e : 0;
        if (ec < E) { sv[j] = ei[ec]; dv[j] = ei[E + ec]; }
        else        { sv[j] = dv[j] = ec - E; }
    }

    float4 a[4]; float p[4];
    #pragma unroll
    for (int j = 0; j < 4; j++) {
        a[j] = *reinterpret_cast<const float4*>(xl + (size_t)sv[j] * 128 + lane * 4);
        float4 b = *reinterpret_cast<const float4*>(xr + (size_t)dv[j] * 128 + lane * 4);
        p[j] = lrelu(a[j].x + b.x) * av.x + lrelu(a[j].y + b.y) * av.y
             + lrelu(a[j].z + b.z) * av.z + lrelu(a[j].w + b.w) * av.w;
    }
    #pragma unroll
    for (int o = 1; o < 8; o <<= 1) {
        #pragma unroll
        for (int j = 0; j < 4; j++)
            p[j] += __shfl_xor_sync(0xffffffffu, p[j], o);
    }
    #pragma unroll
    for (int j = 0; j < 4; j++) {
        if (ok[j]) {
            float q = __expf(p[j]);
            float4 v = a[j];
            v.x *= q; v.y *= q; v.z *= q; v.w *= q;
            red_add_v4(acc + (size_t)dv[j] * 128 + lane * 4, v);
            if ((lane & 7) == 0) atomicAdd(&sumb[(size_t)dv[j] * 4 + h], q);
        }
    }
}

// ---- fused edge pass, H=1, C=40 (4 edges per warp: 2 x 16-lane groups x2) --
__global__ void edge_h1(const float* __restrict__ xl, const float* __restrict__ xr,
                        const int* __restrict__ ei, int E, int ET,
                        const float* __restrict__ att,
                        float* __restrict__ acc, float* __restrict__ sumb)
{
    unsigned gw = (blockIdx.x * (unsigned)blockDim.x + threadIdx.x) >> 5;
    int lane = threadIdx.x & 31;
    int grp  = lane >> 4;
    int gl   = lane & 15;
    int base = (int)(gw * 4) + grp;
    float4 t = make_float4(0.f, 0.f, 0.f, 0.f);
    if (gl < 10) t = *reinterpret_cast<const float4*>(att + gl * 4);

    #pragma unroll
    for (int j = 0; j < 2; j++) {
        int e = base + 2 * j;
        bool valid = (e < ET);
        int ec = valid ? e : 0;
        int src, dst;
        if (ec < E) { src = ei[ec]; dst = ei[E + ec]; } else { src = dst = ec - E; }

        float p = 0.f;
        float4 a = make_float4(0.f, 0.f, 0.f, 0.f);
        if (gl < 10) {
            a = *reinterpret_cast<const float4*>(xl + (size_t)src * 40 + gl * 4);
            float4 b = *reinterpret_cast<const float4*>(xr + (size_t)dst * 40 + gl * 4);
            p = lrelu(a.x + b.x) * t.x + lrelu(a.y + b.y) * t.y
              + lrelu(a.z + b.z) * t.z + lrelu(a.w + b.w) * t.w;
        }
        #pragma unroll
        for (int o = 8; o >= 1; o >>= 1)
            p += __shfl_xor_sync(0xffffffffu, p, o);
        if (valid && gl < 10) {
            float q = __expf(p);
            a.x *= q; a.y *= q; a.z *= q; a.w *= q;
            red_add_v4(acc + (size_t)dst * 40 + gl * 4, a);
            if (gl == 0) atomicAdd(&sumb[dst], q);
        }
    }
}

// ---------------- epilogues: divide by sum, add bias, (ELU) ------------------
__global__ void div_bias_elu4(const float4* __restrict__ in, const float* __restrict__ sumb,
                              const float4* __restrict__ bias, float4* __restrict__ out,
                              int total4)
{
    int i = blockIdx.x * blockDim.x + threadIdx.x;
    if (i >= total4) return;
    int n = i >> 5, c = i & 31;
    float inv = 1.f / __ldg(&sumb[n * 4 + (c >> 3)]);
    float4 v = in[i], b = bias[c];
    v.x = v.x * inv + b.x; v.y = v.y * inv + b.y;
    v.z = v.z * inv + b.z; v.w = v.w * inv + b.w;
    v.x = v.x > 0.f ? v.x : expm1f(v.x);
    v.y = v.y > 0.f ? v.y : expm1f(v.y);
    v.z = v.z > 0.f ? v.z : expm1f(v.z);
    v.w = v.w > 0.f ? v.w : expm1f(v.w);
    out[i] = v;
}

__global__ void div_bias40_4(const float4* __restrict__ in, const float* __restrict__ sumb,
                             const float4* __restrict__ bias, float4* __restrict__ out,
                             int total4)
{
    int i = blockIdx.x * blockDim.x + threadIdx.x;
    if (i >= total4) return;
    int n = i / 10, c = i % 10;
    float inv = 1.f / __ldg(&sumb[n]);
    float4 v = in[i], b = bias[c];
    v.x = v.x * inv + b.x; v.y = v.y * inv + b.y;
    v.z = v.z * inv + b.z; v.w = v.w * inv + b.w;
    out[i] = v;
}

// ---------------- host orchestration ----------------------------------------
static inline int ceil_div(int a, int b) { return (a + b - 1) / b; }

extern "C" void kernel_launch(void* const* d_in, const int* in_sizes, int n_in,
                              void* d_out, int out_size)
{
    const float* x   = (const float*)d_in[0];
    const int*   ei  = (const int*)  d_in[1];
    const float* W1l = (const float*)d_in[2];
    const float* b1l = (const float*)d_in[3];
    const float* W1r = (const float*)d_in[4];
    const float* b1r = (const float*)d_in[5];
    const float* at1 = (const float*)d_in[6];
    const float* bs1 = (const float*)d_in[7];
    const float* W2l = (const float*)d_in[8];
    const float* b2l = (const float*)d_in[9];
    const float* W2r = (const float*)d_in[10];
    const float* b2r = (const float*)d_in[11];
    const float* at2 = (const float*)d_in[12];
    const float* bs2 = (const float*)d_in[13];
    const float* W3l = (const float*)d_in[14];
    const float* b3l = (const float*)d_in[15];
    const float* W3r = (const float*)d_in[16];
    const float* b3r = (const float*)d_in[17];
    const float* at3 = (const float*)d_in[18];
    const float* bs3 = (const float*)d_in[19];
    float* out = (float*)d_out;

    const int N  = in_sizes[0] / 128;
    const int E  = in_sizes[1] / 2;
    const int ET = E + N;

    float *xl, *xr, *h, *acc, *sum;
    cudaGetSymbolAddress((void**)&xl,  g_xl);
    cudaGetSymbolAddress((void**)&xr,  g_xr);
    cudaGetSymbolAddress((void**)&h,   g_h);
    cudaGetSymbolAddress((void**)&acc, g_acc);
    cudaGetSymbolAddress((void**)&sum, g_sum);

    // gemm<16,8,3>: W 128x128 (64K) + bias 128 + xs 64x36 (9.2K) = ~75KB, 3 CTA/SM
    const int SM12 = (128 * 128 + 128 + 64 * 36) * 4;    // 75264 B
    // gemm<10,16,2>: W 128x80 (40K) + bias 80 + xs 128x36 (18.4K) = ~59KB, 2 CTA/SM
    const int SM3  = (128 * 80 + 80 + 128 * 36) * 4;     // 59712 B
    cudaFuncSetAttribute(gemm_dual<16, 8, 3>,  cudaFuncAttributeMaxDynamicSharedMemorySize, SM12);
    cudaFuncSetAttribute(gemm_dual<10, 16, 2>, cudaFuncAttributeMaxDynamicSharedMemorySize, SM3);

    const dim3 g12(222, 2);   // 444 blocks = 3/SM, col-split in y
    const dim3 g3(296, 1);    // 2/SM

    const int edgeBlocks = ceil_div(ET, 32);   // 4 edges/warp, 8 warps/block

    // ===== layer 1 (H=4, C=32) =====
    gemm_dual<16, 8, 3><<<g12, 128, SM12>>>(x, N, W1l, b1l, W1r, b1r, 128, xl, xr);
    cudaMemsetAsync(sum, 0, (size_t)N * 4 * sizeof(float));
    cudaMemsetAsync(acc, 0, (size_t)N * 128 * sizeof(float));
    edge_h4<<<edgeBlocks, 256>>>(xl, xr, ei, E, ET, at1, acc, sum);
    div_bias_elu4<<<ceil_div(N * 32, 256), 256>>>((const float4*)acc, sum,
                                                  (const float4*)bs1, (float4*)h, N * 32);

    // ===== layer 2 (H=4, C=32) =====
    gemm_dual<16, 8, 3><<<g12, 128, SM12>>>(h, N, W2l, b2l, W2r, b2r, 128, xl, xr);
    cudaMemsetAsync(sum, 0, (size_t)N * 4 * sizeof(float));
    cudaMemsetAsync(acc, 0, (size_t)N * 128 * sizeof(float));
    edge_h4<<<edgeBlocks, 256>>>(xl, xr, ei, E, ET, at2, acc, sum);
    div_bias_elu4<<<ceil_div(N * 32, 256), 256>>>((const float4*)acc, sum,
                                                  (const float4*)bs2, (float4*)h, N * 32);

    // ===== layer 3 (H=1, C=40) =====
    gemm_dual<10, 16, 2><<<g3, 160, SM3>>>(h, N, W3l, b3l, W3r, b3r, 40, xl, xr);
    cudaMemsetAsync(sum, 0, (size_t)N * sizeof(float));
    cudaMemsetAsync(acc, 0, (size_t)N * 40 * sizeof(float));
    edge_h1<<<edgeBlocks, 256>>>(xl, xr, ei, E, ET, at3, acc, sum);
    div_bias40_4<<<ceil_div(N * 10, 256), 256>>>((const float4*)acc, sum,
                                                 (const float4*)bs3, (float4*)out, N * 10);
}

// round 11
// speedup vs baseline: 1.9129x; 1.0484x over previous
#include <cuda_runtime.h>
#include <cstdint>

#define NMAX 100000
#define EMAX 1000000
#define ETMAX (EMAX + NMAX)

// ---------------- scratch (device globals: allocation-free rule) -------------
__device__ float g_xl[(size_t)NMAX * 128];
__device__ float g_xr[(size_t)NMAX * 128];
__device__ float g_h [(size_t)NMAX * 128];
__device__ float g_acc[(size_t)NMAX * 128];
__device__ float g_sum[(size_t)NMAX * 4];

// ---------------- helpers ----------------------------------------------------
typedef unsigned long long u64;

__device__ __forceinline__ float lrelu(float v) { return v > 0.f ? v : 0.2f * v; }

__device__ __forceinline__ void red_add_v4(float* p, float4 v) {
    asm volatile("red.global.add.v4.f32 [%0], {%1,%2,%3,%4};"
                 :: "l"(p), "f"(v.x), "f"(v.y), "f"(v.z), "f"(v.w) : "memory");
}

__device__ __forceinline__ u64 pack_dup(float x) {
    u64 r; asm("mov.b64 %0, {%1, %1};" : "=l"(r) : "f"(x)); return r;
}
__device__ __forceinline__ void ffma2(u64& d, u64 a, u64 b) {
    asm("fma.rn.f32x2 %0, %1, %2, %0;" : "+l"(d) : "l"(a), "l"(b));
}
__device__ __forceinline__ float2 unpack2(u64 v) {
    float2 f; asm("mov.b64 {%0, %1}, %2;" : "=f"(f.x), "=f"(f.y) : "l"(v)); return f;
}
__device__ __forceinline__ u64 d2l(double d) { return __double_as_longlong(d); }

// ---------------- fused dual GEMM, column-split + K-chunked ------------------
// Block covers JB = COLG*8 output cols at blockIdx.y*JB. Each thread owns
// 8 rows x 8 cols, but the 8 cols are TWO float4 groups: cols [cg*4, cg*4+4)
// and [COLG*4 + cg*4, ...+4). This makes every W LDS.128 touch 16B-stride
// addresses -> one conflict-free wavefront. x tile is padded 16B per 8-row
// group so the 4 rg's in a warp land on distinct bank quads.
template<int COLG, int ROWG, int MAXCTA>
__global__ __launch_bounds__(COLG * ROWG, MAXCTA)
void gemm_dual(const float* __restrict__ in, int N,
               const float* __restrict__ Wl, const float* __restrict__ bl,
               const float* __restrict__ Wr, const float* __restrict__ br,
               int Jhalf,
               float* __restrict__ xl, float* __restrict__ xr)
{
    constexpr int JB    = COLG * 8;
    constexpr int HALF  = COLG * 4;     // offset of the second col group
    constexpr int RPT   = ROWG * 8;
    constexpr int KC    = 32;
    constexpr int XS    = KC + 4;       // 36 floats/row
    constexpr int XTOT  = RPT * XS + (RPT / 8) * 4;
    extern __shared__ float sm[];
    float* Wt   = sm;                   // [128][JB]  k-major
    float* bcol = Wt + 128 * JB;        // [JB]
    float* xs   = bcol + JB;            // padded [RPT][XS]

    const int tid    = threadIdx.x;
    const int nth    = blockDim.x;
    const int coloff = blockIdx.y * JB;

    for (int idx = tid; idx < 128 * JB; idx += nth) {
        int k = idx / JB, jl = idx % JB;
        int j = coloff + jl;
        Wt[idx] = (j < Jhalf) ? Wl[j * 128 + k] : Wr[(j - Jhalf) * 128 + k];
    }
    for (int jl = tid; jl < JB; jl += nth) {
        int j = coloff + jl;
        bcol[jl] = (j < Jhalf) ? bl[j] : br[j - Jhalf];
    }
    __syncthreads();

    const int cg = tid % COLG;
    const int rg = tid / COLG;
    const int ntiles = (N + RPT - 1) / RPT;
    const float4* in4 = reinterpret_cast<const float4*>(in);

    for (int tile = blockIdx.x; tile < ntiles; tile += gridDim.x) {
        const int r0 = tile * RPT;

        u64 acc2[8][4];
        #pragma unroll
        for (int r = 0; r < 8; r++)
            #pragma unroll
            for (int c = 0; c < 4; c++) acc2[r][c] = 0ull;

        // padded x row base for this thread's 8-row group
        const float* xsb = xs + (rg * 8) * XS + rg * 4;
        const float* wbA = Wt + cg * 4;
        const float* wbB = Wt + HALF + cg * 4;

        #pragma unroll
        for (int ch = 0; ch < 128 / KC; ch++) {
            for (int idx = tid; idx < RPT * (KC / 4); idx += nth) {
                int r = idx >> 3, q = idx & 7;      // KC/4 == 8
                int row = r0 + r;
                float4 v = (row < N) ? in4[(size_t)row * 32 + ch * (KC / 4) + q]
                                     : make_float4(0.f, 0.f, 0.f, 0.f);
                *reinterpret_cast<float4*>(xs + r * XS + (r >> 3) * 4 + q * 4) = v;
            }
            __syncthreads();

            const int kb = ch * KC;
            for (int k = 0; k < KC; k += 4) {
                float4 xv[8];
                #pragma unroll
                for (int r = 0; r < 8; r++)
                    xv[r] = *reinterpret_cast<const float4*>(xsb + r * XS + k);
                #pragma unroll
                for (int kk = 0; kk < 4; kk++) {
                    const int krow = (kb + k + kk) * JB;
                    double2 wA = *reinterpret_cast<const double2*>(wbA + krow);
                    double2 wB = *reinterpret_cast<const double2*>(wbB + krow);
                    u64 w0 = d2l(wA.x), w1 = d2l(wA.y);
                    u64 w2 = d2l(wB.x), w3 = d2l(wB.y);
                    #pragma unroll
                    for (int r = 0; r < 8; r++) {
                        float xk = (kk == 0) ? xv[r].x : (kk == 1) ? xv[r].y
                                 : (kk == 2) ? xv[r].z : xv[r].w;
                        u64 xx = pack_dup(xk);
                        ffma2(acc2[r][0], w0, xx);
                        ffma2(acc2[r][1], w1, xx);
                        ffma2(acc2[r][2], w2, xx);
                        ffma2(acc2[r][3], w3, xx);
                    }
                }
            }
            __syncthreads();
        }

        // two col groups: A at coloff+cg*4, B at coloff+HALF+cg*4
        const int jA = coloff + cg * 4;
        const int jB = coloff + HALF + cg * 4;
        float4 bvA = *reinterpret_cast<const float4*>(bcol + cg * 4);
        float4 bvB = *reinterpret_cast<const float4*>(bcol + HALF + cg * 4);
        float* baseA; int joA;
        if (jA < Jhalf) { baseA = xl; joA = jA; } else { baseA = xr; joA = jA - Jhalf; }
        float* baseB; int joB;
        if (jB < Jhalf) { baseB = xl; joB = jB; } else { baseB = xr; joB = jB - Jhalf; }

        #pragma unroll
        for (int r = 0; r < 8; r++) {
            int row = r0 + rg * 8 + r;
            if (row < N) {
                float2 c0 = unpack2(acc2[r][0]);
                float2 c1 = unpack2(acc2[r][1]);
                float2 c2 = unpack2(acc2[r][2]);
                float2 c3 = unpack2(acc2[r][3]);
                *reinterpret_cast<float4*>(baseA + (size_t)row * Jhalf + joA) =
                    make_float4(c0.x + bvA.x, c0.y + bvA.y, c1.x + bvA.z, c1.y + bvA.w);
                *reinterpret_cast<float4*>(baseB + (size_t)row * Jhalf + joB) =
                    make_float4(c2.x + bvB.x, c2.y + bvB.y, c3.x + bvB.z, c3.y + bvB.w);
            }
        }
    }
}

// ---- fused edge pass, H=4, C=32 (4 edges per warp) -------------------------
__global__ void edge_h4(const float* __restrict__ xl, const float* __restrict__ xr,
                        const int* __restrict__ ei, int E, int ET,
                        const float* __restrict__ att,
                        float* __restrict__ acc, float* __restrict__ sumb)
{
    unsigned gw = (blockIdx.x * (unsigned)blockDim.x + threadIdx.x) >> 5;
    int base = (int)(gw * 4);
    if (base >= ET) return;
    int lane = threadIdx.x & 31;
    int h = lane >> 3;
    float4 av = *reinterpret_cast<const float4*>(att + lane * 4);

    int sv[4], dv[4]; bool ok[4];
    #pragma unroll
    for (int j = 0; j < 4; j++) {
        int e = base + j;
        ok[j] = (e < ET);
        int ec = ok[j] ? e : 0;
        if (ec < E) { sv[j] = ei[ec]; dv[j] = ei[E + ec]; }
        else        { sv[j] = dv[j] = ec - E; }
    }

    float4 a[4]; float p[4];
    #pragma unroll
    for (int j = 0; j < 4; j++) {
        a[j] = *reinterpret_cast<const float4*>(xl + (size_t)sv[j] * 128 + lane * 4);
        float4 b = *reinterpret_cast<const float4*>(xr + (size_t)dv[j] * 128 + lane * 4);
        p[j] = lrelu(a[j].x + b.x) * av.x + lrelu(a[j].y + b.y) * av.y
             + lrelu(a[j].z + b.z) * av.z + lrelu(a[j].w + b.w) * av.w;
    }
    #pragma unroll
    for (int o = 1; o < 8; o <<= 1) {
        #pragma unroll
        for (int j = 0; j < 4; j++)
            p[j] += __shfl_xor_sync(0xffffffffu, p[j], o);
    }
    #pragma unroll
    for (int j = 0; j < 4; j++) {
        if (ok[j]) {
            float q = __expf(p[j]);
            float4 v = a[j];
            v.x *= q; v.y *= q; v.z *= q; v.w *= q;
            red_add_v4(acc + (size_t)dv[j] * 128 + lane * 4, v);
            if ((lane & 7) == 0) atomicAdd(&sumb[(size_t)dv[j] * 4 + h], q);
        }
    }
}

// ---- fused edge pass, H=1, C=40 (4 edges per warp: 2 x 16-lane groups x2) --
__global__ void edge_h1(const float* __restrict__ xl, const float* __restrict__ xr,
                        const int* __restrict__ ei, int E, int ET,
                        const float* __restrict__ att,
                        float* __restrict__ acc, float* __restrict__ sumb)
{
    unsigned gw = (blockIdx.x * (unsigned)blockDim.x + threadIdx.x) >> 5;
    int lane = threadIdx.x & 31;
    int grp  = lane >> 4;
    int gl   = lane & 15;
    int base = (int)(gw * 4) + grp;
    float4 t = make_float4(0.f, 0.f, 0.f, 0.f);
    if (gl < 10) t = *reinterpret_cast<const float4*>(att + gl * 4);

    #pragma unroll
    for (int j = 0; j < 2; j++) {
        int e = base + 2 * j;
        bool valid = (e < ET);
        int ec = valid ? e : 0;
        int src, dst;
        if (ec < E) { src = ei[ec]; dst = ei[E + ec]; } else { src = dst = ec - E; }

        float p = 0.f;
        float4 a = make_float4(0.f, 0.f, 0.f, 0.f);
        if (gl < 10) {
            a = *reinterpret_cast<const float4*>(xl + (size_t)src * 40 + gl * 4);
            float4 b = *reinterpret_cast<const float4*>(xr + (size_t)dst * 40 + gl * 4);
            p = lrelu(a.x + b.x) * t.x + lrelu(a.y + b.y) * t.y
              + lrelu(a.z + b.z) * t.z + lrelu(a.w + b.w) * t.w;
        }
        #pragma unroll
        for (int o = 8; o >= 1; o >>= 1)
            p += __shfl_xor_sync(0xffffffffu, p, o);
        if (valid && gl < 10) {
            float q = __expf(p);
            a.x *= q; a.y *= q; a.z *= q; a.w *= q;
            red_add_v4(acc + (size_t)dst * 40 + gl * 4, a);
            if (gl == 0) atomicAdd(&sumb[dst], q);
        }
    }
}

// ---------------- epilogues: divide by sum, add bias, (ELU) ------------------
__global__ void div_bias_elu4(const float4* __restrict__ in, const float* __restrict__ sumb,
                              const float4* __restrict__ bias, float4* __restrict__ out,
                              int total4)
{
    int i = blockIdx.x * blockDim.x + threadIdx.x;
    if (i >= total4) return;
    int n = i >> 5, c = i & 31;
    float inv = 1.f / __ldg(&sumb[n * 4 + (c >> 3)]);
    float4 v = in[i], b = bias[c];
    v.x = v.x * inv + b.x; v.y = v.y * inv + b.y;
    v.z = v.z * inv + b.z; v.w = v.w * inv + b.w;
    v.x = v.x > 0.f ? v.x : expm1f(v.x);
    v.y = v.y > 0.f ? v.y : expm1f(v.y);
    v.z = v.z > 0.f ? v.z : expm1f(v.z);
    v.w = v.w > 0.f ? v.w : expm1f(v.w);
    out[i] = v;
}

__global__ void div_bias40_4(const float4* __restrict__ in, const float* __restrict__ sumb,
                             const float4* __restrict__ bias, float4* __restrict__ out,
                             int total4)
{
    int i = blockIdx.x * blockDim.x + threadIdx.x;
    if (i >= total4) return;
    int n = i / 10, c = i % 10;
    float inv = 1.f / __ldg(&sumb[n]);
    float4 v = in[i], b = bias[c];
    v.x = v.x * inv + b.x; v.y = v.y * inv + b.y;
    v.z = v.z * inv + b.z; v.w = v.w * inv + b.w;
    out[i] = v;
}

// ---------------- host orchestration ----------------------------------------
static inline int ceil_div(int a, int b) { return (a + b - 1) / b; }

extern "C" void kernel_launch(void* const* d_in, const int* in_sizes, int n_in,
                              void* d_out, int out_size)
{
    const float* x   = (const float*)d_in[0];
    const int*   ei  = (const int*)  d_in[1];
    const float* W1l = (const float*)d_in[2];
    const float* b1l = (const float*)d_in[3];
    const float* W1r = (const float*)d_in[4];
    const float* b1r = (const float*)d_in[5];
    const float* at1 = (const float*)d_in[6];
    const float* bs1 = (const float*)d_in[7];
    const float* W2l = (const float*)d_in[8];
    const float* b2l = (const float*)d_in[9];
    const float* W2r = (const float*)d_in[10];
    const float* b2r = (const float*)d_in[11];
    const float* at2 = (const float*)d_in[12];
    const float* bs2 = (const float*)d_in[13];
    const float* W3l = (const float*)d_in[14];
    const float* b3l = (const float*)d_in[15];
    const float* W3r = (const float*)d_in[16];
    const float* b3r = (const float*)d_in[17];
    const float* at3 = (const float*)d_in[18];
    const float* bs3 = (const float*)d_in[19];
    float* out = (float*)d_out;

    const int N  = in_sizes[0] / 128;
    const int E  = in_sizes[1] / 2;
    const int ET = E + N;

    float *xl, *xr, *h, *acc, *sum;
    cudaGetSymbolAddress((void**)&xl,  g_xl);
    cudaGetSymbolAddress((void**)&xr,  g_xr);
    cudaGetSymbolAddress((void**)&h,   g_h);
    cudaGetSymbolAddress((void**)&acc, g_acc);
    cudaGetSymbolAddress((void**)&sum, g_sum);

    // gemm<8,16,3>: W 128x64 (32K) + bias 64 + xs 128x36+64 (18.7K) = ~51KB, 3 CTA/SM
    const int SM12 = (128 * 64 + 64 + (128 * 36 + 64)) * 4;   // 51712 B
    // gemm<10,16,2>: W 128x80 (40K) + bias 80 + xs (18.7K) = ~60KB, 2 CTA/SM
    const int SM3  = (128 * 80 + 80 + (128 * 36 + 64)) * 4;   // 59968 B
    cudaFuncSetAttribute(gemm_dual<8, 16, 3>,  cudaFuncAttributeMaxDynamicSharedMemorySize, SM12);
    cudaFuncSetAttribute(gemm_dual<10, 16, 2>, cudaFuncAttributeMaxDynamicSharedMemorySize, SM3);

    const dim3 g12(111, 4);   // 444 blocks = 3/SM, 4 col-splits of 64
    const dim3 g3(296, 1);    // 2/SM, JB=80 covers both halves

    const int edgeBlocks = ceil_div(ET, 32);   // 4 edges/warp, 8 warps/block

    // ===== layer 1 (H=4, C=32) =====
    gemm_dual<8, 16, 3><<<g12, 128, SM12>>>(x, N, W1l, b1l, W1r, b1r, 128, xl, xr);
    cudaMemsetAsync(sum, 0, (size_t)N * 4 * sizeof(float));
    cudaMemsetAsync(acc, 0, (size_t)N * 128 * sizeof(float));
    edge_h4<<<edgeBlocks, 256>>>(xl, xr, ei, E, ET, at1, acc, sum);
    div_bias_elu4<<<ceil_div(N * 32, 256), 256>>>((const float4*)acc, sum,
                                                  (const float4*)bs1, (float4*)h, N * 32);

    // ===== layer 2 (H=4, C=32) =====
    gemm_dual<8, 16, 3><<<g12, 128, SM12>>>(h, N, W2l, b2l, W2r, b2r, 128, xl, xr);
    cudaMemsetAsync(sum, 0, (size_t)N * 4 * sizeof(float));
    cudaMemsetAsync(acc, 0, (size_t)N * 128 * sizeof(float));
    edge_h4<<<edgeBlocks, 256>>>(xl, xr, ei, E, ET, at2, acc, sum);
    div_bias_elu4<<<ceil_div(N * 32, 256), 256>>>((const float4*)acc, sum,
                                                  (const float4*)bs2, (float4*)h, N * 32);

    // ===== layer 3 (H=1, C=40) =====
    gemm_dual<10, 16, 2><<<g3, 160, SM3>>>(h, N, W3l, b3l, W3r, b3r, 40, xl, xr);
    cudaMemsetAsync(sum, 0, (size_t)N * sizeof(float));
    cudaMemsetAsync(acc, 0, (size_t)N * 40 * sizeof(float));
    edge_h1<<<edgeBlocks, 256>>>(xl, xr, ei, E, ET, at3, acc, sum);
    div_bias40_4<<<ceil_div(N * 10, 256), 256>>>((const float4*)acc, sum,
                                                 (const float4*)bs3, (float4*)out, N * 10);
}

// round 14
// speedup vs baseline: 2.1443x; 1.1210x over previous
#include <cuda_runtime.h>
#include <cstdint>

#define NMAX 100000
#define EMAX 1000000

// ---------------- scratch (device globals: allocation-free rule) -------------
__device__ float g_xl[(size_t)NMAX * 128];
__device__ float g_xr[(size_t)NMAX * 128];
__device__ float g_h [(size_t)NMAX * 128];
__device__ int   g_deg[NMAX + 1];
__device__ int   g_off[NMAX + 1];
__device__ int   g_cur[NMAX];
__device__ int   g_csr[EMAX];

// ---------------- helpers ----------------------------------------------------
typedef unsigned long long u64;

__device__ __forceinline__ float lrelu(float v) { return v > 0.f ? v : 0.2f * v; }

__device__ __forceinline__ u64 pack_dup(float x) {
    u64 r; asm("mov.b64 %0, {%1, %1};" : "=l"(r) : "f"(x)); return r;
}
__device__ __forceinline__ void ffma2(u64& d, u64 a, u64 b) {
    asm("fma.rn.f32x2 %0, %1, %2, %0;" : "+l"(d) : "l"(a), "l"(b));
}
__device__ __forceinline__ float2 unpack2(u64 v) {
    float2 f; asm("mov.b64 {%0, %1}, %2;" : "=f"(f.x), "=f"(f.y) : "l"(v)); return f;
}
__device__ __forceinline__ u64 d2l(double d) { return __double_as_longlong(d); }

// ---------------- fused dual GEMM, column-split + K-chunked ------------------
// (unchanged from R11 passing kernel)
template<int COLG, int ROWG, int MAXCTA>
__global__ __launch_bounds__(COLG * ROWG, MAXCTA)
void gemm_dual(const float* __restrict__ in, int N,
               const float* __restrict__ Wl, const float* __restrict__ bl,
               const float* __restrict__ Wr, const float* __restrict__ br,
               int Jhalf,
               float* __restrict__ xl, float* __restrict__ xr)
{
    constexpr int JB    = COLG * 8;
    constexpr int HALF  = COLG * 4;
    constexpr int RPT   = ROWG * 8;
    constexpr int KC    = 32;
    constexpr int XS    = KC + 4;
    extern __shared__ float sm[];
    float* Wt   = sm;
    float* bcol = Wt + 128 * JB;
    float* xs   = bcol + JB;

    const int tid    = threadIdx.x;
    const int nth    = blockDim.x;
    const int coloff = blockIdx.y * JB;

    for (int idx = tid; idx < 128 * JB; idx += nth) {
        int k = idx / JB, jl = idx % JB;
        int j = coloff + jl;
        Wt[idx] = (j < Jhalf) ? Wl[j * 128 + k] : Wr[(j - Jhalf) * 128 + k];
    }
    for (int jl = tid; jl < JB; jl += nth) {
        int j = coloff + jl;
        bcol[jl] = (j < Jhalf) ? bl[j] : br[j - Jhalf];
    }
    __syncthreads();

    const int cg = tid % COLG;
    const int rg = tid / COLG;
    const int ntiles = (N + RPT - 1) / RPT;
    const float4* in4 = reinterpret_cast<const float4*>(in);

    for (int tile = blockIdx.x; tile < ntiles; tile += gridDim.x) {
        const int r0 = tile * RPT;

        u64 acc2[8][4];
        #pragma unroll
        for (int r = 0; r < 8; r++)
            #pragma unroll
            for (int c = 0; c < 4; c++) acc2[r][c] = 0ull;

        const float* xsb = xs + (rg * 8) * XS + rg * 4;
        const float* wbA = Wt + cg * 4;
        const float* wbB = Wt + HALF + cg * 4;

        #pragma unroll
        for (int ch = 0; ch < 128 / KC; ch++) {
            for (int idx = tid; idx < RPT * (KC / 4); idx += nth) {
                int r = idx >> 3, q = idx & 7;
                int row = r0 + r;
                float4 v = (row < N) ? in4[(size_t)row * 32 + ch * (KC / 4) + q]
                                     : make_float4(0.f, 0.f, 0.f, 0.f);
                *reinterpret_cast<float4*>(xs + r * XS + (r >> 3) * 4 + q * 4) = v;
            }
            __syncthreads();

            const int kb = ch * KC;
            for (int k = 0; k < KC; k += 4) {
                float4 xv[8];
                #pragma unroll
                for (int r = 0; r < 8; r++)
                    xv[r] = *reinterpret_cast<const float4*>(xsb + r * XS + k);
                #pragma unroll
                for (int kk = 0; kk < 4; kk++) {
                    const int krow = (kb + k + kk) * JB;
                    double2 wA = *reinterpret_cast<const double2*>(wbA + krow);
                    double2 wB = *reinterpret_cast<const double2*>(wbB + krow);
                    u64 w0 = d2l(wA.x), w1 = d2l(wA.y);
                    u64 w2 = d2l(wB.x), w3 = d2l(wB.y);
                    #pragma unroll
                    for (int r = 0; r < 8; r++) {
                        float xk = (kk == 0) ? xv[r].x : (kk == 1) ? xv[r].y
                                 : (kk == 2) ? xv[r].z : xv[r].w;
                        u64 xx = pack_dup(xk);
                        ffma2(acc2[r][0], w0, xx);
                        ffma2(acc2[r][1], w1, xx);
                        ffma2(acc2[r][2], w2, xx);
                        ffma2(acc2[r][3], w3, xx);
                    }
                }
            }
            __syncthreads();
        }

        const int jA = coloff + cg * 4;
        const int jB = coloff + HALF + cg * 4;
        float4 bvA = *reinterpret_cast<const float4*>(bcol + cg * 4);
        float4 bvB = *reinterpret_cast<const float4*>(bcol + HALF + cg * 4);
        float* baseA; int joA;
        if (jA < Jhalf) { baseA = xl; joA = jA; } else { baseA = xr; joA = jA - Jhalf; }
        float* baseB; int joB;
        if (jB < Jhalf) { baseB = xl; joB = jB; } else { baseB = xr; joB = jB - Jhalf; }

        #pragma unroll
        for (int r = 0; r < 8; r++) {
            int row = r0 + rg * 8 + r;
            if (row < N) {
                float2 c0 = unpack2(acc2[r][0]);
                float2 c1 = unpack2(acc2[r][1]);
                float2 c2 = unpack2(acc2[r][2]);
                float2 c3 = unpack2(acc2[r][3]);
                *reinterpret_cast<float4*>(baseA + (size_t)row * Jhalf + joA) =
                    make_float4(c0.x + bvA.x, c0.y + bvA.y, c1.x + bvA.z, c1.y + bvA.w);
                *reinterpret_cast<float4*>(baseB + (size_t)row * Jhalf + joB) =
                    make_float4(c2.x + bvB.x, c2.y + bvB.y, c3.x + bvB.z, c3.y + bvB.w);
            }
        }
    }
}

// ---------------- CSR build: histogram -> scan -> scatter --------------------
__global__ void hist_deg(const int* __restrict__ ei, int E, int* __restrict__ deg)
{
    int e = blockIdx.x * blockDim.x + threadIdx.x;
    if (e < E) atomicAdd(&deg[ei[E + e]], 1);
}

// single-block exclusive scan over deg[0..N) -> off, cur; off[N] = total
__global__ void scan_off(const int* __restrict__ deg, int* __restrict__ off,
                         int* __restrict__ cur, int N)
{
    __shared__ int wsum[32];
    __shared__ int carry_s;
    int tid = threadIdx.x, lane = tid & 31, wid = tid >> 5;
    if (tid == 0) carry_s = 0;
    __syncthreads();
    for (int base = 0; base < N; base += 1024) {
        int i = base + tid;
        int v = (i < N) ? deg[i] : 0;
        int x = v;
        #pragma unroll
        for (int o = 1; o < 32; o <<= 1) {
            int t = __shfl_up_sync(0xffffffffu, x, o);
            if (lane >= o) x += t;
        }
        if (lane == 31) wsum[wid] = x;
        __syncthreads();
        if (wid == 0) {
            int y = wsum[lane];
            #pragma unroll
            for (int o = 1; o < 32; o <<= 1) {
                int t = __shfl_up_sync(0xffffffffu, y, o);
                if (lane >= o) y += t;
            }
            wsum[lane] = y;
        }
        __syncthreads();
        int wb = (wid > 0) ? wsum[wid - 1] : 0;
        int carry = carry_s;
        int excl = carry + wb + x - v;
        if (i < N) { off[i] = excl; cur[i] = excl; }
        __syncthreads();
        if (tid == 1023) carry_s = carry + wsum[31];
        __syncthreads();
    }
    if (threadIdx.x == 0) off[N] = carry_s;
}

__global__ void scatter_csr(const int* __restrict__ ei, int E,
                            int* __restrict__ cur, int* __restrict__ csr)
{
    int e = blockIdx.x * blockDim.x + threadIdx.x;
    if (e < E) {
        int d = ei[E + e];
        int pos = atomicAdd(&cur[d], 1);
        csr[pos] = ei[e];
    }
}

// ---------------- pull aggregation, H=4, C=32 (warp per dst) -----------------
// out[dst] = (self + sum_in exp(s)*xl[src]) / (sum exp) + bias, optional ELU.
template<bool DO_ELU>
__global__ void pull_h4(const float* __restrict__ xl, const float* __restrict__ xr,
                        const int* __restrict__ off, const int* __restrict__ csr,
                        const float* __restrict__ att, const float* __restrict__ bias,
                        float* __restrict__ out, int N)
{
    int w = (int)((blockIdx.x * (unsigned)blockDim.x + threadIdx.x) >> 5);
    if (w >= N) return;
    int lane = threadIdx.x & 31;
    float4 av  = *reinterpret_cast<const float4*>(att + lane * 4);
    float4 xr4 = *reinterpret_cast<const float4*>(xr + (size_t)w * 128 + lane * 4);
    float4 bv  = *reinterpret_cast<const float4*>(bias + lane * 4);

    // self loop first
    float4 a = *reinterpret_cast<const float4*>(xl + (size_t)w * 128 + lane * 4);
    float p = lrelu(a.x + xr4.x) * av.x + lrelu(a.y + xr4.y) * av.y
            + lrelu(a.z + xr4.z) * av.z + lrelu(a.w + xr4.w) * av.w;
    p += __shfl_xor_sync(0xffffffffu, p, 1);
    p += __shfl_xor_sync(0xffffffffu, p, 2);
    p += __shfl_xor_sync(0xffffffffu, p, 4);
    float q = __expf(p);
    float4 acc = make_float4(q * a.x, q * a.y, q * a.z, q * a.w);
    float ssum = q;

    int beg = off[w], end = off[w + 1];
    float4 an = make_float4(0.f, 0.f, 0.f, 0.f);
    if (beg < end) {
        int s = csr[beg];
        an = *reinterpret_cast<const float4*>(xl + (size_t)s * 128 + lane * 4);
    }
    for (int i = beg; i < end; i++) {
        a = an;
        if (i + 1 < end) {
            int s = csr[i + 1];
            an = *reinterpret_cast<const float4*>(xl + (size_t)s * 128 + lane * 4);
        }
        p = lrelu(a.x + xr4.x) * av.x + lrelu(a.y + xr4.y) * av.y
          + lrelu(a.z + xr4.z) * av.z + lrelu(a.w + xr4.w) * av.w;
        p += __shfl_xor_sync(0xffffffffu, p, 1);
        p += __shfl_xor_sync(0xffffffffu, p, 2);
        p += __shfl_xor_sync(0xffffffffu, p, 4);
        q = __expf(p);
        acc.x += q * a.x; acc.y += q * a.y; acc.z += q * a.z; acc.w += q * a.w;
        ssum += q;
    }

    float inv = 1.f / ssum;
    float4 o = make_float4(acc.x * inv + bv.x, acc.y * inv + bv.y,
                           acc.z * inv + bv.z, acc.w * inv + bv.w);
    if (DO_ELU) {
        o.x = o.x > 0.f ? o.x : expm1f(o.x);
        o.y = o.y > 0.f ? o.y : expm1f(o.y);
        o.z = o.z > 0.f ? o.z : expm1f(o.z);
        o.w = o.w > 0.f ? o.w : expm1f(o.w);
    }
    *reinterpret_cast<float4*>(out + (size_t)w * 128 + lane * 4) = o;
}

// ---------------- pull aggregation, H=1, C=40 (2 dsts per warp) --------------
__global__ void pull_h1(const float* __restrict__ xl, const float* __restrict__ xr,
                        const int* __restrict__ off, const int* __restrict__ csr,
                        const float* __restrict__ att, const float* __restrict__ bias,
                        float* __restrict__ out, int N)
{
    unsigned gw = (blockIdx.x * (unsigned)blockDim.x + threadIdx.x) >> 5;
    int lane = threadIdx.x & 31;
    int grp  = lane >> 4;
    int gl   = lane & 15;
    int d = (int)(gw * 2) + grp;
    bool vd = (d < N);
    int dc = vd ? d : 0;
    bool al = vd && (gl < 10);

    float4 z = make_float4(0.f, 0.f, 0.f, 0.f);
    float4 t   = al ? *reinterpret_cast<const float4*>(att + gl * 4) : z;
    float4 xr4 = al ? *reinterpret_cast<const float4*>(xr + (size_t)dc * 40 + gl * 4) : z;
    float4 bv  = al ? *reinterpret_cast<const float4*>(bias + gl * 4) : z;

    // self loop
    float4 a = al ? *reinterpret_cast<const float4*>(xl + (size_t)dc * 40 + gl * 4) : z;
    float p = al ? (lrelu(a.x + xr4.x) * t.x + lrelu(a.y + xr4.y) * t.y
                  + lrelu(a.z + xr4.z) * t.z + lrelu(a.w + xr4.w) * t.w) : 0.f;
    p += __shfl_xor_sync(0xffffffffu, p, 8);
    p += __shfl_xor_sync(0xffffffffu, p, 4);
    p += __shfl_xor_sync(0xffffffffu, p, 2);
    p += __shfl_xor_sync(0xffffffffu, p, 1);
    float q = __expf(p);
    float4 acc = make_float4(q * a.x, q * a.y, q * a.z, q * a.w);
    float ssum = q;

    int beg = vd ? off[d] : 0;
    int end = vd ? off[d + 1] : 0;
    int cnt = end - beg;
    int other = __shfl_xor_sync(0xffffffffu, cnt, 16);
    int mx = cnt > other ? cnt : other;

    for (int j = 0; j < mx; j++) {
        bool act = (j < cnt);
        float4 aa = z;
        float pp = 0.f;
        if (act && gl < 10) {
            int s = csr[beg + j];
            aa = *reinterpret_cast<const float4*>(xl + (size_t)s * 40 + gl * 4);
            pp = lrelu(aa.x + xr4.x) * t.x + lrelu(aa.y + xr4.y) * t.y
               + lrelu(aa.z + xr4.z) * t.z + lrelu(aa.w + xr4.w) * t.w;
        }
        pp += __shfl_xor_sync(0xffffffffu, pp, 8);
        pp += __shfl_xor_sync(0xffffffffu, pp, 4);
        pp += __shfl_xor_sync(0xffffffffu, pp, 2);
        pp += __shfl_xor_sync(0xffffffffu, pp, 1);
        float qq = __expf(pp);
        if (act) {
            acc.x += qq * aa.x; acc.y += qq * aa.y;
            acc.z += qq * aa.z; acc.w += qq * aa.w;
            ssum += qq;
        }
    }

    if (al) {
        float inv = 1.f / ssum;
        float4 o = make_float4(acc.x * inv + bv.x, acc.y * inv + bv.y,
                               acc.z * inv + bv.z, acc.w * inv + bv.w);
        *reinterpret_cast<float4*>(out + (size_t)dc * 40 + gl * 4) = o;
    }
}

// ---------------- host orchestration ----------------------------------------
static inline int ceil_div(int a, int b) { return (a + b - 1) / b; }

extern "C" void kernel_launch(void* const* d_in, const int* in_sizes, int n_in,
                              void* d_out, int out_size)
{
    const float* x   = (const float*)d_in[0];
    const int*   ei  = (const int*)  d_in[1];
    const float* W1l = (const float*)d_in[2];
    const float* b1l = (const float*)d_in[3];
    const float* W1r = (const float*)d_in[4];
    const float* b1r = (const float*)d_in[5];
    const float* at1 = (const float*)d_in[6];
    const float* bs1 = (const float*)d_in[7];
    const float* W2l = (const float*)d_in[8];
    const float* b2l = (const float*)d_in[9];
    const float* W2r = (const float*)d_in[10];
    const float* b2r = (const float*)d_in[11];
    const float* at2 = (const float*)d_in[12];
    const float* bs2 = (const float*)d_in[13];
    const float* W3l = (const float*)d_in[14];
    const float* b3l = (const float*)d_in[15];
    const float* W3r = (const float*)d_in[16];
    const float* b3r = (const float*)d_in[17];
    const float* at3 = (const float*)d_in[18];
    const float* bs3 = (const float*)d_in[19];
    float* out = (float*)d_out;

    const int N  = in_sizes[0] / 128;
    const int E  = in_sizes[1] / 2;

    float *xl, *xr, *h;
    int *deg, *off, *cur, *csr;
    cudaGetSymbolAddress((void**)&xl,  g_xl);
    cudaGetSymbolAddress((void**)&xr,  g_xr);
    cudaGetSymbolAddress((void**)&h,   g_h);
    cudaGetSymbolAddress((void**)&deg, g_deg);
    cudaGetSymbolAddress((void**)&off, g_off);
    cudaGetSymbolAddress((void**)&cur, g_cur);
    cudaGetSymbolAddress((void**)&csr, g_csr);

    const int SM12 = (128 * 64 + 64 + (128 * 36 + 64)) * 4;   // 51712 B
    const int SM3  = (128 * 80 + 80 + (128 * 36 + 64)) * 4;   // 59968 B
    cudaFuncSetAttribute(gemm_dual<8, 16, 3>,  cudaFuncAttributeMaxDynamicSharedMemorySize, SM12);
    cudaFuncSetAttribute(gemm_dual<10, 16, 2>, cudaFuncAttributeMaxDynamicSharedMemorySize, SM3);

    const dim3 g12(111, 4);   // 444 blocks = 3/SM
    const dim3 g3(296, 1);

    // ===== CSR build (reused by all 3 layers) =====
    cudaMemsetAsync(deg, 0, (size_t)N * sizeof(int));
    hist_deg<<<ceil_div(E, 256), 256>>>(ei, E, deg);
    scan_off<<<1, 1024>>>(deg, off, cur, N);
    scatter_csr<<<ceil_div(E, 256), 256>>>(ei, E, cur, csr);

    const int pullBlocks4 = ceil_div(N * 32, 256);        // warp per dst
    const int pullBlocks1 = ceil_div(ceil_div(N, 2) * 32, 256);

    // ===== layer 1 (H=4, C=32) =====
    gemm_dual<8, 16, 3><<<g12, 128, SM12>>>(x, N, W1l, b1l, W1r, b1r, 128, xl, xr);
    pull_h4<true><<<pullBlocks4, 256>>>(xl, xr, off, csr, at1, bs1, h, N);

    // ===== layer 2 (H=4, C=32) =====
    gemm_dual<8, 16, 3><<<g12, 128, SM12>>>(h, N, W2l, b2l, W2r, b2r, 128, xl, xr);
    pull_h4<true><<<pullBlocks4, 256>>>(xl, xr, off, csr, at2, bs2, h, N);

    // ===== layer 3 (H=1, C=40) =====
    gemm_dual<10, 16, 2><<<g3, 160, SM3>>>(h, N, W3l, b3l, W3r, b3r, 40, xl, xr);
    pull_h1<<<pullBlocks1, 256>>>(xl, xr, off, csr, at3, bs3, out, N);
}